// round 3
// baseline (speedup 1.0000x reference)
#include <cuda_runtime.h>
#include <cuda_bf16.h>
#include <cstdint>
#include <cstddef>

#define D_MODEL 1024
#define N_HEADS 16
#define BATCH   4
#define SEQ     2048
#define DK      64
#define M_ROWS  (BATCH * SEQ)   // 8192

// ---------------------------------------------------------------------------
// Scratch (static device arrays — allocation-free per harness rules)
// ---------------------------------------------------------------------------
__device__ __nv_bfloat16 g_xh[M_ROWS * D_MODEL];
__device__ __nv_bfloat16 g_xl[M_ROWS * D_MODEL];
__device__ __nv_bfloat16 g_wt[8 * D_MODEL * D_MODEL]; // wq_h,wq_l,wk_h,wk_l,wv_h,wv_l,wo_h,wo_l ([N,K] transposed)
__device__ float g_Q[BATCH * N_HEADS * SEQ * DK];     // [B,H,T,dk] fp32
__device__ float g_K[BATCH * N_HEADS * SEQ * DK];
__device__ float g_V[BATCH * N_HEADS * SEQ * DK];
__device__ __nv_bfloat16 g_ah[M_ROWS * D_MODEL];      // attention out hi
__device__ __nv_bfloat16 g_al[M_ROWS * D_MODEL];      // attention out lo

// ---------------------------------------------------------------------------
// PTX helpers (sm_80-compatible path: ldmatrix + mma.sync + cp.async)
// ---------------------------------------------------------------------------
__device__ __forceinline__ uint32_t smem_u32(const void* p) {
    uint32_t a;
    asm("{ .reg .u64 t; cvta.to.shared.u64 t, %1; cvt.u32.u64 %0, t; }" : "=r"(a) : "l"(p));
    return a;
}

#define CP_ASYNC16(dst, src) \
    asm volatile("cp.async.ca.shared.global [%0], [%1], 16;" :: "r"(dst), "l"(src))
#define CP_COMMIT()  asm volatile("cp.async.commit_group;" ::: "memory")
#define CP_WAIT(n)   asm volatile("cp.async.wait_group %0;" :: "n"(n) : "memory")

#define LDMX4(r0, r1, r2, r3, addr) \
    asm volatile("ldmatrix.sync.aligned.m8n8.x4.shared.b16 {%0,%1,%2,%3}, [%4];" \
        : "=r"(r0), "=r"(r1), "=r"(r2), "=r"(r3) : "r"(addr))

#define MMA16816(acc, a, b0, b1) \
    asm volatile("mma.sync.aligned.m16n8k16.row.col.f32.bf16.bf16.f32 " \
        "{%0,%1,%2,%3},{%4,%5,%6,%7},{%8,%9},{%0,%1,%2,%3};" \
        : "+f"((acc)[0]), "+f"((acc)[1]), "+f"((acc)[2]), "+f"((acc)[3]) \
        : "r"((a)[0]), "r"((a)[1]), "r"((a)[2]), "r"((a)[3]), "r"(b0), "r"(b1))

// ---------------------------------------------------------------------------
// Split / transpose conversion kernels
// ---------------------------------------------------------------------------
__global__ __launch_bounds__(256) void splitf(const float* __restrict__ in,
                                              __nv_bfloat16* __restrict__ hi,
                                              __nv_bfloat16* __restrict__ lo, int n4)
{
    int i = blockIdx.x * 256 + threadIdx.x;
    if (i >= n4) return;
    float4 v = ((const float4*)in)[i];
    float vv[4] = {v.x, v.y, v.z, v.w};
    __nv_bfloat16 h[4], l[4];
    #pragma unroll
    for (int k = 0; k < 4; k++) {
        h[k] = __float2bfloat16_rn(vv[k]);
        l[k] = __float2bfloat16_rn(vv[k] - __bfloat162float(h[k]));
    }
    uint2 hp, lp;
    ((__nv_bfloat16*)&hp)[0]=h[0]; ((__nv_bfloat16*)&hp)[1]=h[1];
    ((__nv_bfloat16*)&hp)[2]=h[2]; ((__nv_bfloat16*)&hp)[3]=h[3];
    ((__nv_bfloat16*)&lp)[0]=l[0]; ((__nv_bfloat16*)&lp)[1]=l[1];
    ((__nv_bfloat16*)&lp)[2]=l[2]; ((__nv_bfloat16*)&lp)[3]=l[3];
    ((uint2*)hi)[i] = hp;
    ((uint2*)lo)[i] = lp;
}

// W[K][N] fp32 -> hiT/loT[N][K] bf16 (transpose + split)
__global__ void wsplitT(const float* __restrict__ W,
                        __nv_bfloat16* __restrict__ hiT,
                        __nv_bfloat16* __restrict__ loT)
{
    __shared__ float t[32][33];
    int tx = threadIdx.x, ty = threadIdx.y;
    int n0 = blockIdx.x * 32, k0 = blockIdx.y * 32;
    #pragma unroll
    for (int j = 0; j < 32; j += 8)
        t[ty + j][tx] = W[(size_t)(k0 + ty + j) * D_MODEL + n0 + tx];
    __syncthreads();
    #pragma unroll
    for (int j = 0; j < 32; j += 8) {
        float v = t[tx][ty + j];
        __nv_bfloat16 h = __float2bfloat16_rn(v);
        size_t idx = (size_t)(n0 + ty + j) * D_MODEL + k0 + tx;
        hiT[idx] = h;
        loT[idx] = __float2bfloat16_rn(v - __bfloat162float(h));
    }
}

// ---------------------------------------------------------------------------
// HMMA split-bf16 GEMM: out[M,N] = A[M,K] @ B^T + bias  (B given as [N,K])
// D = Ah·Bh + Ah·Bl + Al·Bh.  CTA tile 128x128, BK=32, cp.async double buffer.
// 8 warps as 2(M) x 4(N): warp tile 64x32 = 4x4 m16n8 frags.
// ---------------------------------------------------------------------------
#define TKk 32
#define NKT (D_MODEL / TKk)     // 32
#define SMSTR 40                // halves per row (32 data + 8 pad) = 80 bytes
#define TILEB (128 * SMSTR * 2) // 10240 bytes per buffer
#define STAGEB (4 * TILEB)      // Ah, Al, Bh, Bl = 40960
#define GEMM_SMEM (2 * STAGEB)  // 81920

__device__ __forceinline__ void load_stage(
    uint32_t smbase,
    const __nv_bfloat16* __restrict__ Ah, const __nv_bfloat16* __restrict__ Al,
    const __nv_bfloat16* __restrict__ Bh, const __nv_bfloat16* __restrict__ Bl,
    int m0, int n0, int k0, int tid)
{
    #pragma unroll
    for (int t = 0; t < 2; t++) {
        const int idx = tid + t * 256;
        const int row = idx >> 2;
        const int c16 = idx & 3;
        const uint32_t so = (uint32_t)(row * (SMSTR * 2) + c16 * 16);
        const size_t ga = (size_t)(m0 + row) * D_MODEL + k0 + c16 * 8;
        const size_t gb = (size_t)(n0 + row) * D_MODEL + k0 + c16 * 8;
        CP_ASYNC16(smbase + 0 * TILEB + so, Ah + ga);
        CP_ASYNC16(smbase + 1 * TILEB + so, Al + ga);
        CP_ASYNC16(smbase + 2 * TILEB + so, Bh + gb);
        CP_ASYNC16(smbase + 3 * TILEB + so, Bl + gb);
    }
}

__global__ __launch_bounds__(256) void gemm_hmma(
    const __nv_bfloat16* __restrict__ Ah, const __nv_bfloat16* __restrict__ Al,
    const __nv_bfloat16* __restrict__ Bh, const __nv_bfloat16* __restrict__ Bl,
    const float* __restrict__ bias, float* __restrict__ out, int split)
{
    extern __shared__ char sm[];
    const uint32_t smb = smem_u32(sm);
    const int tid = threadIdx.x;
    const int wid = tid >> 5;
    const int lane = tid & 31;
    const int warp_m = wid & 1;      // 0..1
    const int warp_n = wid >> 1;     // 0..3
    const int m0 = blockIdx.y * 128;
    const int n0 = blockIdx.x * 128;

    // ldmatrix per-lane addressing: row = lane&15, col-half-offset = (lane>>4)*8
    const int lrow = lane & 15;
    const int lcol = (lane >> 4) * 8;

    uint32_t aAddr[4], bAddr[2];
    #pragma unroll
    for (int mi = 0; mi < 4; mi++)
        aAddr[mi] = smb + (uint32_t)(((warp_m * 64 + mi * 16 + lrow) * SMSTR + lcol) * 2);
    #pragma unroll
    for (int p = 0; p < 2; p++)
        bAddr[p] = smb + (uint32_t)(((warp_n * 32 + p * 16 + lrow) * SMSTR + lcol) * 2);

    float acc[4][4][4];
    #pragma unroll
    for (int i = 0; i < 4; i++)
        #pragma unroll
        for (int j = 0; j < 4; j++)
            #pragma unroll
            for (int r = 0; r < 4; r++) acc[i][j][r] = 0.f;

    load_stage(smb, Ah, Al, Bh, Bl, m0, n0, 0, tid);
    CP_COMMIT();

    for (int kt = 0; kt < NKT; kt++) {
        const uint32_t stoff = (uint32_t)((kt & 1) * STAGEB);
        if (kt + 1 < NKT) {
            load_stage(smb + (uint32_t)(((kt + 1) & 1) * STAGEB),
                       Ah, Al, Bh, Bl, m0, n0, (kt + 1) * TKk, tid);
            CP_COMMIT();
            CP_WAIT(1);
        } else {
            CP_WAIT(0);
        }
        __syncthreads();

        #pragma unroll
        for (int ks = 0; ks < 2; ks++) {
            const uint32_t ko = stoff + (uint32_t)(ks * 32);  // 16 halves = 32 bytes
            uint32_t a[4][4], b[2][4];

            // pass 1: Ah x Bh
            #pragma unroll
            for (int mi = 0; mi < 4; mi++)
                LDMX4(a[mi][0], a[mi][1], a[mi][2], a[mi][3], aAddr[mi] + ko);
            #pragma unroll
            for (int p = 0; p < 2; p++)
                LDMX4(b[p][0], b[p][1], b[p][2], b[p][3], bAddr[p] + ko + 2 * TILEB);
            #pragma unroll
            for (int mi = 0; mi < 4; mi++)
                #pragma unroll
                for (int ni = 0; ni < 4; ni++)
                    MMA16816(acc[mi][ni], a[mi], b[ni >> 1][ni & 1], b[ni >> 1][2 + (ni & 1)]);

            // pass 2: Ah x Bl
            #pragma unroll
            for (int p = 0; p < 2; p++)
                LDMX4(b[p][0], b[p][1], b[p][2], b[p][3], bAddr[p] + ko + 3 * TILEB);
            #pragma unroll
            for (int mi = 0; mi < 4; mi++)
                #pragma unroll
                for (int ni = 0; ni < 4; ni++)
                    MMA16816(acc[mi][ni], a[mi], b[ni >> 1][ni & 1], b[ni >> 1][2 + (ni & 1)]);

            // pass 3: Al x Bh
            #pragma unroll
            for (int mi = 0; mi < 4; mi++)
                LDMX4(a[mi][0], a[mi][1], a[mi][2], a[mi][3], aAddr[mi] + ko + 1 * TILEB);
            #pragma unroll
            for (int p = 0; p < 2; p++)
                LDMX4(b[p][0], b[p][1], b[p][2], b[p][3], bAddr[p] + ko + 2 * TILEB);
            #pragma unroll
            for (int mi = 0; mi < 4; mi++)
                #pragma unroll
                for (int ni = 0; ni < 4; ni++)
                    MMA16816(acc[mi][ni], a[mi], b[ni >> 1][ni & 1], b[ni >> 1][2 + (ni & 1)]);
        }
        __syncthreads();
    }

    // epilogue: d-frag layout lane: g=lane>>2, t=lane&3
    const int g = lane >> 2;
    const int t = lane & 3;
    #pragma unroll
    for (int mi = 0; mi < 4; mi++) {
        #pragma unroll
        for (int ni = 0; ni < 4; ni++) {
            const int n = n0 + warp_n * 32 + ni * 8 + t * 2;
            const float b0 = bias[n], b1 = bias[n + 1];
            #pragma unroll
            for (int half = 0; half < 2; half++) {
                const int m = m0 + warp_m * 64 + mi * 16 + g + half * 8;
                const float v0 = acc[mi][ni][half * 2 + 0] + b0;
                const float v1 = acc[mi][ni][half * 2 + 1] + b1;
                if (split) {
                    const int bb = m >> 11;
                    const int tt = m & (SEQ - 1);
                    const int h  = n >> 6;
                    const int dd = n & (DK - 1);
                    float* o = &out[(((size_t)bb * N_HEADS + h) * SEQ + tt) * DK + dd];
                    o[0] = v0; o[1] = v1;
                } else {
                    float* o = &out[(size_t)m * D_MODEL + n];
                    o[0] = v0; o[1] = v1;
                }
            }
        }
    }
}

// ---------------------------------------------------------------------------
// Flash-style causal attention (fp32 FFMA), emits bf16 hi/lo for final GEMM.
// ---------------------------------------------------------------------------
#define AQ  64
#define AKV 64
#define SMS 65

__global__ __launch_bounds__(256) void attn_kernel(
    const float* __restrict__ Q, const float* __restrict__ K,
    const float* __restrict__ V,
    __nv_bfloat16* __restrict__ outh, __nv_bfloat16* __restrict__ outl)
{
    extern __shared__ float smf[];
    float* Qs = smf;
    float* Ks = Qs + AQ  * SMS;
    float* Vs = Ks + AKV * SMS;
    float* Ps = Vs + AKV * SMS;

    const int bh = blockIdx.y;
    const int qt = blockIdx.x;
    const int q0 = qt * AQ;
    const int tid = threadIdx.x;
    const int tx  = tid & 15;
    const int ty  = tid >> 4;

    const float* Qb = Q + (size_t)bh * SEQ * DK;
    const float* Kb = K + (size_t)bh * SEQ * DK;
    const float* Vb = V + (size_t)bh * SEQ * DK;

    for (int idx = tid; idx < AQ * (DK / 4); idx += 256) {
        const int r = idx >> 4;
        const int c = (idx & 15) << 2;
        float4 v = *(const float4*)&Qb[(size_t)(q0 + r) * DK + c];
        float* p = &Qs[r * SMS + c];
        p[0] = v.x; p[1] = v.y; p[2] = v.z; p[3] = v.w;
    }

    float m_i[4], l_i[4], acc[4][4];
    #pragma unroll
    for (int i = 0; i < 4; i++) {
        m_i[i] = -1e30f; l_i[i] = 0.f;
        #pragma unroll
        for (int j = 0; j < 4; j++) acc[i][j] = 0.f;
    }

    for (int kt = 0; kt <= qt; kt++) {
        const int k0 = kt * AKV;
        __syncthreads();

        for (int idx = tid; idx < AKV * (DK / 4); idx += 256) {
            const int r = idx >> 4;
            const int c = (idx & 15) << 2;
            float4 kv = *(const float4*)&Kb[(size_t)(k0 + r) * DK + c];
            float* pk = &Ks[r * SMS + c];
            pk[0] = kv.x; pk[1] = kv.y; pk[2] = kv.z; pk[3] = kv.w;
            float4 vv = *(const float4*)&Vb[(size_t)(k0 + r) * DK + c];
            float* pv = &Vs[r * SMS + c];
            pv[0] = vv.x; pv[1] = vv.y; pv[2] = vv.z; pv[3] = vv.w;
        }
        __syncthreads();

        float s[4][4];
        #pragma unroll
        for (int i = 0; i < 4; i++)
            #pragma unroll
            for (int j = 0; j < 4; j++) s[i][j] = 0.f;

        #pragma unroll 4
        for (int kk = 0; kk < DK; kk++) {
            float a[4], b[4];
            #pragma unroll
            for (int i = 0; i < 4; i++) a[i] = Qs[(ty * 4 + i) * SMS + kk];
            #pragma unroll
            for (int j = 0; j < 4; j++) b[j] = Ks[(tx * 4 + j) * SMS + kk];
            #pragma unroll
            for (int i = 0; i < 4; i++)
                #pragma unroll
                for (int j = 0; j < 4; j++)
                    s[i][j] = fmaf(a[i], b[j], s[i][j]);
        }

        const bool diag = (kt == qt);
        float rmax[4];
        #pragma unroll
        for (int i = 0; i < 4; i++) {
            const int qi = q0 + ty * 4 + i;
            #pragma unroll
            for (int j = 0; j < 4; j++) {
                float v = s[i][j] * 0.125f;
                if (diag && (k0 + tx * 4 + j) > qi) v = -1e30f;
                s[i][j] = v;
            }
            rmax[i] = fmaxf(fmaxf(s[i][0], s[i][1]), fmaxf(s[i][2], s[i][3]));
        }
        #pragma unroll
        for (int off = 8; off >= 1; off >>= 1)
            #pragma unroll
            for (int i = 0; i < 4; i++)
                rmax[i] = fmaxf(rmax[i], __shfl_xor_sync(0xffffffffu, rmax[i], off));

        float rsum[4];
        #pragma unroll
        for (int i = 0; i < 4; i++) {
            const float mnew = fmaxf(m_i[i], rmax[i]);
            const float sc   = __expf(m_i[i] - mnew);
            float rs = 0.f;
            #pragma unroll
            for (int j = 0; j < 4; j++) {
                const float p = __expf(s[i][j] - mnew);
                s[i][j] = p;
                rs += p;
            }
            rsum[i] = rs;
            m_i[i] = mnew;
            l_i[i] *= sc;
            #pragma unroll
            for (int j = 0; j < 4; j++) acc[i][j] *= sc;
        }
        #pragma unroll
        for (int off = 8; off >= 1; off >>= 1)
            #pragma unroll
            for (int i = 0; i < 4; i++)
                rsum[i] += __shfl_xor_sync(0xffffffffu, rsum[i], off);
        #pragma unroll
        for (int i = 0; i < 4; i++) l_i[i] += rsum[i];

        #pragma unroll
        for (int i = 0; i < 4; i++)
            #pragma unroll
            for (int j = 0; j < 4; j++)
                Ps[(ty * 4 + i) * SMS + tx * 4 + j] = s[i][j];
        __syncthreads();

        #pragma unroll 4
        for (int c = 0; c < AKV; c++) {
            float p[4], v[4];
            #pragma unroll
            for (int i = 0; i < 4; i++) p[i] = Ps[(ty * 4 + i) * SMS + c];
            #pragma unroll
            for (int j = 0; j < 4; j++) v[j] = Vs[c * SMS + tx * 4 + j];
            #pragma unroll
            for (int i = 0; i < 4; i++)
                #pragma unroll
                for (int j = 0; j < 4; j++)
                    acc[i][j] = fmaf(p[i], v[j], acc[i][j]);
        }
    }

    const int b = bh >> 4;
    const int h = bh & (N_HEADS - 1);
    #pragma unroll
    for (int i = 0; i < 4; i++) {
        const int t = q0 + ty * 4 + i;
        const float inv = 1.0f / l_i[i];
        #pragma unroll
        for (int j = 0; j < 4; j++) {
            const int d = tx * 4 + j;
            const float v = acc[i][j] * inv;
            const size_t idx = ((size_t)(b * SEQ + t)) * D_MODEL + h * DK + d;
            const __nv_bfloat16 hv = __float2bfloat16_rn(v);
            outh[idx] = hv;
            outl[idx] = __float2bfloat16_rn(v - __bfloat162float(hv));
        }
    }
}

// ---------------------------------------------------------------------------
extern "C" void kernel_launch(void* const* d_in, const int* in_sizes, int n_in,
                              void* d_out, int out_size)
{
    const float* x   = (const float*)d_in[0];
    const float* w_q = (const float*)d_in[2];
    const float* b_q = (const float*)d_in[3];
    const float* w_k = (const float*)d_in[4];
    const float* b_k = (const float*)d_in[5];
    const float* w_v = (const float*)d_in[6];
    const float* b_v = (const float*)d_in[7];
    const float* w_o = (const float*)d_in[8];
    const float* b_o = (const float*)d_in[9];
    float* out = (float*)d_out;

    __nv_bfloat16 *xh, *xl, *wt, *ah, *al;
    float *Qp, *Kp, *Vp;
    cudaGetSymbolAddress((void**)&xh, g_xh);
    cudaGetSymbolAddress((void**)&xl, g_xl);
    cudaGetSymbolAddress((void**)&wt, g_wt);
    cudaGetSymbolAddress((void**)&Qp, g_Q);
    cudaGetSymbolAddress((void**)&Kp, g_K);
    cudaGetSymbolAddress((void**)&Vp, g_V);
    cudaGetSymbolAddress((void**)&ah, g_ah);
    cudaGetSymbolAddress((void**)&al, g_al);

    const size_t WSZ = (size_t)D_MODEL * D_MODEL;
    __nv_bfloat16 *wqh = wt,           *wql = wt + WSZ;
    __nv_bfloat16 *wkh = wt + 2 * WSZ, *wkl = wt + 3 * WSZ;
    __nv_bfloat16 *wvh = wt + 4 * WSZ, *wvl = wt + 5 * WSZ;
    __nv_bfloat16 *woh = wt + 6 * WSZ, *wol = wt + 7 * WSZ;

    cudaFuncSetAttribute(gemm_hmma, cudaFuncAttributeMaxDynamicSharedMemorySize, GEMM_SMEM);
    const int attn_smem = 4 * AQ * SMS * (int)sizeof(float);
    cudaFuncSetAttribute(attn_kernel, cudaFuncAttributeMaxDynamicSharedMemorySize, attn_smem);

    // conversions
    const int n4 = M_ROWS * D_MODEL / 4;
    splitf<<<(n4 + 255) / 256, 256>>>(x, xh, xl, n4);
    dim3 wb(32, 8), wg(D_MODEL / 32, D_MODEL / 32);
    wsplitT<<<wg, wb>>>(w_q, wqh, wql);
    wsplitT<<<wg, wb>>>(w_k, wkh, wkl);
    wsplitT<<<wg, wb>>>(w_v, wvh, wvl);
    wsplitT<<<wg, wb>>>(w_o, woh, wol);

    // projections (HMMA)
    dim3 gg(D_MODEL / 128, M_ROWS / 128);  // (8, 64)
    gemm_hmma<<<gg, 256, GEMM_SMEM>>>(xh, xl, wqh, wql, b_q, Qp, 1);
    gemm_hmma<<<gg, 256, GEMM_SMEM>>>(xh, xl, wkh, wkl, b_k, Kp, 1);
    gemm_hmma<<<gg, 256, GEMM_SMEM>>>(xh, xl, wvh, wvl, b_v, Vp, 1);

    // attention (fp32), emits bf16 hi/lo
    attn_kernel<<<dim3(SEQ / AQ, BATCH * N_HEADS), 256, attn_smem>>>(Qp, Kp, Vp, ah, al);

    // output projection (HMMA)
    gemm_hmma<<<gg, 256, GEMM_SMEM>>>(ah, al, woh, wol, b_o, out, 0);
}

// round 4
// speedup vs baseline: 1.5918x; 1.5918x over previous
#include <cuda_runtime.h>
#include <cuda_bf16.h>
#include <cstdint>
#include <cstddef>

#define D_MODEL 1024
#define N_HEADS 16
#define BATCH   4
#define SEQ     2048
#define DK      64
#define M_ROWS  (BATCH * SEQ)   // 8192

// ---------------------------------------------------------------------------
// Scratch (static device arrays — allocation-free per harness rules)
// ---------------------------------------------------------------------------
__device__ __nv_bfloat16 g_xh[M_ROWS * D_MODEL];
__device__ __nv_bfloat16 g_xl[M_ROWS * D_MODEL];
__device__ __nv_bfloat16 g_wt[8 * D_MODEL * D_MODEL]; // wq_h,wq_l,wk_h,wk_l,wv_h,wv_l,wo_h,wo_l ([N,K] transposed)
__device__ float g_Q[BATCH * N_HEADS * SEQ * DK];     // [B,H,T,dk] fp32
__device__ float g_K[BATCH * N_HEADS * SEQ * DK];
__device__ float g_V[BATCH * N_HEADS * SEQ * DK];
__device__ __nv_bfloat16 g_ah[M_ROWS * D_MODEL];      // attention out hi
__device__ __nv_bfloat16 g_al[M_ROWS * D_MODEL];      // attention out lo

// ---------------------------------------------------------------------------
// PTX helpers (sm_80-compatible path: ldmatrix + mma.sync + cp.async)
// ---------------------------------------------------------------------------
__device__ __forceinline__ uint32_t smem_u32(const void* p) {
    uint32_t a;
    asm("{ .reg .u64 t; cvta.to.shared.u64 t, %1; cvt.u32.u64 %0, t; }" : "=r"(a) : "l"(p));
    return a;
}

#define CP_ASYNC16(dst, src) \
    asm volatile("cp.async.ca.shared.global [%0], [%1], 16;" :: "r"(dst), "l"(src))
#define CP_COMMIT()  asm volatile("cp.async.commit_group;" ::: "memory")
#define CP_WAIT(n)   asm volatile("cp.async.wait_group %0;" :: "n"(n) : "memory")

#define LDMX4(r0, r1, r2, r3, addr) \
    asm volatile("ldmatrix.sync.aligned.m8n8.x4.shared.b16 {%0,%1,%2,%3}, [%4];" \
        : "=r"(r0), "=r"(r1), "=r"(r2), "=r"(r3) : "r"(addr))

#define MMA16816(acc, a, b0, b1) \
    asm volatile("mma.sync.aligned.m16n8k16.row.col.f32.bf16.bf16.f32 " \
        "{%0,%1,%2,%3},{%4,%5,%6,%7},{%8,%9},{%0,%1,%2,%3};" \
        : "+f"((acc)[0]), "+f"((acc)[1]), "+f"((acc)[2]), "+f"((acc)[3]) \
        : "r"((a)[0]), "r"((a)[1]), "r"((a)[2]), "r"((a)[3]), "r"(b0), "r"(b1))

// ---------------------------------------------------------------------------
// Split / transpose conversion kernels
// ---------------------------------------------------------------------------
__global__ __launch_bounds__(256) void splitf(const float* __restrict__ in,
                                              __nv_bfloat16* __restrict__ hi,
                                              __nv_bfloat16* __restrict__ lo, int n4)
{
    int i = blockIdx.x * 256 + threadIdx.x;
    if (i >= n4) return;
    float4 v = ((const float4*)in)[i];
    float vv[4] = {v.x, v.y, v.z, v.w};
    __nv_bfloat16 h[4], l[4];
    #pragma unroll
    for (int k = 0; k < 4; k++) {
        h[k] = __float2bfloat16_rn(vv[k]);
        l[k] = __float2bfloat16_rn(vv[k] - __bfloat162float(h[k]));
    }
    uint2 hp, lp;
    ((__nv_bfloat16*)&hp)[0]=h[0]; ((__nv_bfloat16*)&hp)[1]=h[1];
    ((__nv_bfloat16*)&hp)[2]=h[2]; ((__nv_bfloat16*)&hp)[3]=h[3];
    ((__nv_bfloat16*)&lp)[0]=l[0]; ((__nv_bfloat16*)&lp)[1]=l[1];
    ((__nv_bfloat16*)&lp)[2]=l[2]; ((__nv_bfloat16*)&lp)[3]=l[3];
    ((uint2*)hi)[i] = hp;
    ((uint2*)lo)[i] = lp;
}

// W[K][N] fp32 -> hiT/loT[N][K] bf16 (transpose + split)
__global__ void wsplitT(const float* __restrict__ W,
                        __nv_bfloat16* __restrict__ hiT,
                        __nv_bfloat16* __restrict__ loT)
{
    __shared__ float t[32][33];
    int tx = threadIdx.x, ty = threadIdx.y;
    int n0 = blockIdx.x * 32, k0 = blockIdx.y * 32;
    #pragma unroll
    for (int j = 0; j < 32; j += 8)
        t[ty + j][tx] = W[(size_t)(k0 + ty + j) * D_MODEL + n0 + tx];
    __syncthreads();
    #pragma unroll
    for (int j = 0; j < 32; j += 8) {
        float v = t[tx][ty + j];
        __nv_bfloat16 h = __float2bfloat16_rn(v);
        size_t idx = (size_t)(n0 + ty + j) * D_MODEL + k0 + tx;
        hiT[idx] = h;
        loT[idx] = __float2bfloat16_rn(v - __bfloat162float(h));
    }
}

// ---------------------------------------------------------------------------
// HMMA split-bf16 GEMM: out[M,N] = A[M,K] @ B^T + bias  (B given as [N,K])
// D = Ah·Bh + Ah·Bl + Al·Bh.  CTA tile 128x128, BK=32, cp.async double buffer.
// 8 warps as 2(M) x 4(N): warp tile 64x32 = 4x4 m16n8 frags.
// ---------------------------------------------------------------------------
#define TKk 32
#define NKT (D_MODEL / TKk)     // 32
#define SMSTR 40                // halves per row (32 data + 8 pad) = 80 bytes
#define TILEB (128 * SMSTR * 2) // 10240 bytes per buffer
#define STAGEB (4 * TILEB)      // Ah, Al, Bh, Bl = 40960
#define GEMM_SMEM (2 * STAGEB)  // 81920

__device__ __forceinline__ void load_stage(
    uint32_t smbase,
    const __nv_bfloat16* __restrict__ Ah, const __nv_bfloat16* __restrict__ Al,
    const __nv_bfloat16* __restrict__ Bh, const __nv_bfloat16* __restrict__ Bl,
    int m0, int n0, int k0, int tid)
{
    #pragma unroll
    for (int t = 0; t < 2; t++) {
        const int idx = tid + t * 256;
        const int row = idx >> 2;
        const int c16 = idx & 3;
        const uint32_t so = (uint32_t)(row * (SMSTR * 2) + c16 * 16);
        const size_t ga = (size_t)(m0 + row) * D_MODEL + k0 + c16 * 8;
        const size_t gb = (size_t)(n0 + row) * D_MODEL + k0 + c16 * 8;
        CP_ASYNC16(smbase + 0 * TILEB + so, Ah + ga);
        CP_ASYNC16(smbase + 1 * TILEB + so, Al + ga);
        CP_ASYNC16(smbase + 2 * TILEB + so, Bh + gb);
        CP_ASYNC16(smbase + 3 * TILEB + so, Bl + gb);
    }
}

__global__ __launch_bounds__(256) void gemm_hmma(
    const __nv_bfloat16* __restrict__ Ah, const __nv_bfloat16* __restrict__ Al,
    const __nv_bfloat16* __restrict__ Bh, const __nv_bfloat16* __restrict__ Bl,
    const float* __restrict__ bias, float* __restrict__ out, int split)
{
    extern __shared__ char sm[];
    const uint32_t smb = smem_u32(sm);
    const int tid = threadIdx.x;
    const int wid = tid >> 5;
    const int lane = tid & 31;
    const int warp_m = wid & 1;      // 0..1
    const int warp_n = wid >> 1;     // 0..3
    const int m0 = blockIdx.y * 128;
    const int n0 = blockIdx.x * 128;

    // ldmatrix per-lane addressing: row = lane&15, col-half-offset = (lane>>4)*8
    const int lrow = lane & 15;
    const int lcol = (lane >> 4) * 8;

    uint32_t aAddr[4], bAddr[2];
    #pragma unroll
    for (int mi = 0; mi < 4; mi++)
        aAddr[mi] = smb + (uint32_t)(((warp_m * 64 + mi * 16 + lrow) * SMSTR + lcol) * 2);
    #pragma unroll
    for (int p = 0; p < 2; p++)
        bAddr[p] = smb + (uint32_t)(((warp_n * 32 + p * 16 + lrow) * SMSTR + lcol) * 2);

    float acc[4][4][4];
    #pragma unroll
    for (int i = 0; i < 4; i++)
        #pragma unroll
        for (int j = 0; j < 4; j++)
            #pragma unroll
            for (int r = 0; r < 4; r++) acc[i][j][r] = 0.f;

    load_stage(smb, Ah, Al, Bh, Bl, m0, n0, 0, tid);
    CP_COMMIT();

    for (int kt = 0; kt < NKT; kt++) {
        const uint32_t stoff = (uint32_t)((kt & 1) * STAGEB);
        if (kt + 1 < NKT) {
            load_stage(smb + (uint32_t)(((kt + 1) & 1) * STAGEB),
                       Ah, Al, Bh, Bl, m0, n0, (kt + 1) * TKk, tid);
            CP_COMMIT();
            CP_WAIT(1);
        } else {
            CP_WAIT(0);
        }
        __syncthreads();

        #pragma unroll
        for (int ks = 0; ks < 2; ks++) {
            const uint32_t ko = stoff + (uint32_t)(ks * 32);  // 16 halves = 32 bytes
            uint32_t a[4][4], b[2][4];

            // pass 1: Ah x Bh
            #pragma unroll
            for (int mi = 0; mi < 4; mi++)
                LDMX4(a[mi][0], a[mi][1], a[mi][2], a[mi][3], aAddr[mi] + ko);
            #pragma unroll
            for (int p = 0; p < 2; p++)
                LDMX4(b[p][0], b[p][1], b[p][2], b[p][3], bAddr[p] + ko + 2 * TILEB);
            #pragma unroll
            for (int mi = 0; mi < 4; mi++)
                #pragma unroll
                for (int ni = 0; ni < 4; ni++)
                    MMA16816(acc[mi][ni], a[mi], b[ni >> 1][ni & 1], b[ni >> 1][2 + (ni & 1)]);

            // pass 2: Ah x Bl
            #pragma unroll
            for (int p = 0; p < 2; p++)
                LDMX4(b[p][0], b[p][1], b[p][2], b[p][3], bAddr[p] + ko + 3 * TILEB);
            #pragma unroll
            for (int mi = 0; mi < 4; mi++)
                #pragma unroll
                for (int ni = 0; ni < 4; ni++)
                    MMA16816(acc[mi][ni], a[mi], b[ni >> 1][ni & 1], b[ni >> 1][2 + (ni & 1)]);

            // pass 3: Al x Bh
            #pragma unroll
            for (int mi = 0; mi < 4; mi++)
                LDMX4(a[mi][0], a[mi][1], a[mi][2], a[mi][3], aAddr[mi] + ko + 1 * TILEB);
            #pragma unroll
            for (int p = 0; p < 2; p++)
                LDMX4(b[p][0], b[p][1], b[p][2], b[p][3], bAddr[p] + ko + 2 * TILEB);
            #pragma unroll
            for (int mi = 0; mi < 4; mi++)
                #pragma unroll
                for (int ni = 0; ni < 4; ni++)
                    MMA16816(acc[mi][ni], a[mi], b[ni >> 1][ni & 1], b[ni >> 1][2 + (ni & 1)]);
        }
        __syncthreads();
    }

    // epilogue: d-frag layout lane: g=lane>>2, t=lane&3
    const int g = lane >> 2;
    const int t = lane & 3;
    #pragma unroll
    for (int mi = 0; mi < 4; mi++) {
        #pragma unroll
        for (int ni = 0; ni < 4; ni++) {
            const int n = n0 + warp_n * 32 + ni * 8 + t * 2;
            const float b0 = bias[n], b1 = bias[n + 1];
            #pragma unroll
            for (int half = 0; half < 2; half++) {
                const int m = m0 + warp_m * 64 + mi * 16 + g + half * 8;
                const float v0 = acc[mi][ni][half * 2 + 0] + b0;
                const float v1 = acc[mi][ni][half * 2 + 1] + b1;
                if (split) {
                    const int bb = m >> 11;
                    const int tt = m & (SEQ - 1);
                    const int h  = n >> 6;
                    const int dd = n & (DK - 1);
                    float* o = &out[(((size_t)bb * N_HEADS + h) * SEQ + tt) * DK + dd];
                    o[0] = v0; o[1] = v1;
                } else {
                    float* o = &out[(size_t)m * D_MODEL + n];
                    o[0] = v0; o[1] = v1;
                }
            }
        }
    }
}

// ---------------------------------------------------------------------------
// Flash-style causal attention (fp32 FFMA), emits bf16 hi/lo for final GEMM.
// ---------------------------------------------------------------------------
#define AQ  64
#define AKV 64
#define SMS 65

__global__ __launch_bounds__(256) void attn_kernel(
    const float* __restrict__ Q, const float* __restrict__ K,
    const float* __restrict__ V,
    __nv_bfloat16* __restrict__ outh, __nv_bfloat16* __restrict__ outl)
{
    extern __shared__ float smf[];
    float* Qs = smf;
    float* Ks = Qs + AQ  * SMS;
    float* Vs = Ks + AKV * SMS;
    float* Ps = Vs + AKV * SMS;

    const int bh = blockIdx.y;
    const int qt = blockIdx.x;
    const int q0 = qt * AQ;
    const int tid = threadIdx.x;
    const int tx  = tid & 15;
    const int ty  = tid >> 4;

    const float* Qb = Q + (size_t)bh * SEQ * DK;
    const float* Kb = K + (size_t)bh * SEQ * DK;
    const float* Vb = V + (size_t)bh * SEQ * DK;

    for (int idx = tid; idx < AQ * (DK / 4); idx += 256) {
        const int r = idx >> 4;
        const int c = (idx & 15) << 2;
        float4 v = *(const float4*)&Qb[(size_t)(q0 + r) * DK + c];
        float* p = &Qs[r * SMS + c];
        p[0] = v.x; p[1] = v.y; p[2] = v.z; p[3] = v.w;
    }

    float m_i[4], l_i[4], acc[4][4];
    #pragma unroll
    for (int i = 0; i < 4; i++) {
        m_i[i] = -1e30f; l_i[i] = 0.f;
        #pragma unroll
        for (int j = 0; j < 4; j++) acc[i][j] = 0.f;
    }

    for (int kt = 0; kt <= qt; kt++) {
        const int k0 = kt * AKV;
        __syncthreads();

        for (int idx = tid; idx < AKV * (DK / 4); idx += 256) {
            const int r = idx >> 4;
            const int c = (idx & 15) << 2;
            float4 kv = *(const float4*)&Kb[(size_t)(k0 + r) * DK + c];
            float* pk = &Ks[r * SMS + c];
            pk[0] = kv.x; pk[1] = kv.y; pk[2] = kv.z; pk[3] = kv.w;
            float4 vv = *(const float4*)&Vb[(size_t)(k0 + r) * DK + c];
            float* pv = &Vs[r * SMS + c];
            pv[0] = vv.x; pv[1] = vv.y; pv[2] = vv.z; pv[3] = vv.w;
        }
        __syncthreads();

        float s[4][4];
        #pragma unroll
        for (int i = 0; i < 4; i++)
            #pragma unroll
            for (int j = 0; j < 4; j++) s[i][j] = 0.f;

        #pragma unroll 4
        for (int kk = 0; kk < DK; kk++) {
            float a[4], b[4];
            #pragma unroll
            for (int i = 0; i < 4; i++) a[i] = Qs[(ty * 4 + i) * SMS + kk];
            #pragma unroll
            for (int j = 0; j < 4; j++) b[j] = Ks[(tx * 4 + j) * SMS + kk];
            #pragma unroll
            for (int i = 0; i < 4; i++)
                #pragma unroll
                for (int j = 0; j < 4; j++)
                    s[i][j] = fmaf(a[i], b[j], s[i][j]);
        }

        const bool diag = (kt == qt);
        float rmax[4];
        #pragma unroll
        for (int i = 0; i < 4; i++) {
            const int qi = q0 + ty * 4 + i;
            #pragma unroll
            for (int j = 0; j < 4; j++) {
                float v = s[i][j] * 0.125f;
                if (diag && (k0 + tx * 4 + j) > qi) v = -1e30f;
                s[i][j] = v;
            }
            rmax[i] = fmaxf(fmaxf(s[i][0], s[i][1]), fmaxf(s[i][2], s[i][3]));
        }
        #pragma unroll
        for (int off = 8; off >= 1; off >>= 1)
            #pragma unroll
            for (int i = 0; i < 4; i++)
                rmax[i] = fmaxf(rmax[i], __shfl_xor_sync(0xffffffffu, rmax[i], off));

        float rsum[4];
        #pragma unroll
        for (int i = 0; i < 4; i++) {
            const float mnew = fmaxf(m_i[i], rmax[i]);
            const float sc   = __expf(m_i[i] - mnew);
            float rs = 0.f;
            #pragma unroll
            for (int j = 0; j < 4; j++) {
                const float p = __expf(s[i][j] - mnew);
                s[i][j] = p;
                rs += p;
            }
            rsum[i] = rs;
            m_i[i] = mnew;
            l_i[i] *= sc;
            #pragma unroll
            for (int j = 0; j < 4; j++) acc[i][j] *= sc;
        }
        #pragma unroll
        for (int off = 8; off >= 1; off >>= 1)
            #pragma unroll
            for (int i = 0; i < 4; i++)
                rsum[i] += __shfl_xor_sync(0xffffffffu, rsum[i], off);
        #pragma unroll
        for (int i = 0; i < 4; i++) l_i[i] += rsum[i];

        #pragma unroll
        for (int i = 0; i < 4; i++)
            #pragma unroll
            for (int j = 0; j < 4; j++)
                Ps[(ty * 4 + i) * SMS + tx * 4 + j] = s[i][j];
        __syncthreads();

        #pragma unroll 4
        for (int c = 0; c < AKV; c++) {
            float p[4], v[4];
            #pragma unroll
            for (int i = 0; i < 4; i++) p[i] = Ps[(ty * 4 + i) * SMS + c];
            #pragma unroll
            for (int j = 0; j < 4; j++) v[j] = Vs[c * SMS + tx * 4 + j];
            #pragma unroll
            for (int i = 0; i < 4; i++)
                #pragma unroll
                for (int j = 0; j < 4; j++)
                    acc[i][j] = fmaf(p[i], v[j], acc[i][j]);
        }
    }

    const int b = bh >> 4;
    const int h = bh & (N_HEADS - 1);
    #pragma unroll
    for (int i = 0; i < 4; i++) {
        const int t = q0 + ty * 4 + i;
        const float inv = 1.0f / l_i[i];
        #pragma unroll
        for (int j = 0; j < 4; j++) {
            const int d = tx * 4 + j;
            const float v = acc[i][j] * inv;
            const size_t idx = ((size_t)(b * SEQ + t)) * D_MODEL + h * DK + d;
            const __nv_bfloat16 hv = __float2bfloat16_rn(v);
            outh[idx] = hv;
            outl[idx] = __float2bfloat16_rn(v - __bfloat162float(hv));
        }
    }
}

// ---------------------------------------------------------------------------
extern "C" void kernel_launch(void* const* d_in, const int* in_sizes, int n_in,
                              void* d_out, int out_size)
{
    const float* x   = (const float*)d_in[0];
    const float* w_q = (const float*)d_in[2];
    const float* b_q = (const float*)d_in[3];
    const float* w_k = (const float*)d_in[4];
    const float* b_k = (const float*)d_in[5];
    const float* w_v = (const float*)d_in[6];
    const float* b_v = (const float*)d_in[7];
    const float* w_o = (const float*)d_in[8];
    const float* b_o = (const float*)d_in[9];
    float* out = (float*)d_out;

    __nv_bfloat16 *xh, *xl, *wt, *ah, *al;
    float *Qp, *Kp, *Vp;
    cudaGetSymbolAddress((void**)&xh, g_xh);
    cudaGetSymbolAddress((void**)&xl, g_xl);
    cudaGetSymbolAddress((void**)&wt, g_wt);
    cudaGetSymbolAddress((void**)&Qp, g_Q);
    cudaGetSymbolAddress((void**)&Kp, g_K);
    cudaGetSymbolAddress((void**)&Vp, g_V);
    cudaGetSymbolAddress((void**)&ah, g_ah);
    cudaGetSymbolAddress((void**)&al, g_al);

    const size_t WSZ = (size_t)D_MODEL * D_MODEL;
    __nv_bfloat16 *wqh = wt,           *wql = wt + WSZ;
    __nv_bfloat16 *wkh = wt + 2 * WSZ, *wkl = wt + 3 * WSZ;
    __nv_bfloat16 *wvh = wt + 4 * WSZ, *wvl = wt + 5 * WSZ;
    __nv_bfloat16 *woh = wt + 6 * WSZ, *wol = wt + 7 * WSZ;

    cudaFuncSetAttribute(gemm_hmma, cudaFuncAttributeMaxDynamicSharedMemorySize, GEMM_SMEM);
    const int attn_smem = 4 * AQ * SMS * (int)sizeof(float);
    cudaFuncSetAttribute(attn_kernel, cudaFuncAttributeMaxDynamicSharedMemorySize, attn_smem);

    // conversions
    const int n4 = M_ROWS * D_MODEL / 4;
    splitf<<<(n4 + 255) / 256, 256>>>(x, xh, xl, n4);
    dim3 wb(32, 8), wg(D_MODEL / 32, D_MODEL / 32);
    wsplitT<<<wg, wb>>>(w_q, wqh, wql);
    wsplitT<<<wg, wb>>>(w_k, wkh, wkl);
    wsplitT<<<wg, wb>>>(w_v, wvh, wvl);
    wsplitT<<<wg, wb>>>(w_o, woh, wol);

    // projections (HMMA)
    dim3 gg(D_MODEL / 128, M_ROWS / 128);  // (8, 64)
    gemm_hmma<<<gg, 256, GEMM_SMEM>>>(xh, xl, wqh, wql, b_q, Qp, 1);
    gemm_hmma<<<gg, 256, GEMM_SMEM>>>(xh, xl, wkh, wkl, b_k, Kp, 1);
    gemm_hmma<<<gg, 256, GEMM_SMEM>>>(xh, xl, wvh, wvl, b_v, Vp, 1);

    // attention (fp32), emits bf16 hi/lo
    attn_kernel<<<dim3(SEQ / AQ, BATCH * N_HEADS), 256, attn_smem>>>(Qp, Kp, Vp, ah, al);

    // output projection (HMMA)
    gemm_hmma<<<gg, 256, GEMM_SMEM>>>(ah, al, woh, wol, b_o, out, 0);
}

// round 5
// speedup vs baseline: 4.0949x; 2.5725x over previous
#include <cuda_runtime.h>
#include <cuda_fp16.h>
#include <cstdint>
#include <cstddef>

#define D_MODEL 1024
#define N_HEADS 16
#define BATCH   4
#define SEQ     2048
#define DK      64
#define M_ROWS  (BATCH * SEQ)
#define BHT     (64 * SEQ * DK)

__device__ __half g_xh[M_ROWS * D_MODEL];
__device__ __half g_xl[M_ROWS * D_MODEL];
__device__ __half g_w4[4 * D_MODEL * D_MODEL];
__device__ __half g_qh[BHT];
__device__ __half g_ql[BHT];
__device__ __half g_k [BHT];
__device__ __half g_vt[BHT];            // [bh][dk][t]
__device__ __half g_oh[M_ROWS * D_MODEL];
__device__ __half g_ol[M_ROWS * D_MODEL];

__device__ __forceinline__ uint32_t smem_u32(const void* p) {
    uint32_t a;
    asm("{ .reg .u64 t; cvta.to.shared.u64 t, %1; cvt.u32.u64 %0, t; }" : "=r"(a) : "l"(p));
    return a;
}
#define CP_ASYNC16(dst, src) \
    asm volatile("cp.async.cg.shared.global [%0], [%1], 16;" :: "r"(dst), "l"(src))
#define CP_COMMIT()  asm volatile("cp.async.commit_group;" ::: "memory")
#define CP_WAIT(n)   asm volatile("cp.async.wait_group %0;" :: "n"(n) : "memory")
#define LDMX4(r0, r1, r2, r3, addr) \
    asm volatile("ldmatrix.sync.aligned.m8n8.x4.shared.b16 {%0,%1,%2,%3}, [%4];" \
        : "=r"(r0), "=r"(r1), "=r"(r2), "=r"(r3) : "r"(addr))
#define MMA16816(acc, a0, a1, a2, a3, b0, b1) \
    asm volatile("mma.sync.aligned.m16n8k16.row.col.f32.f16.f16.f32 " \
        "{%0,%1,%2,%3},{%4,%5,%6,%7},{%8,%9},{%0,%1,%2,%3};" \
        : "+f"((acc)[0]), "+f"((acc)[1]), "+f"((acc)[2]), "+f"((acc)[3]) \
        : "r"(a0), "r"(a1), "r"(a2), "r"(a3), "r"(b0), "r"(b1))

__device__ __forceinline__ uint32_t packh2(float x, float y) {
    __half2 h = __floats2half2_rn(x, y);
    return *(uint32_t*)&h;
}
__device__ __forceinline__ void split_store(__half* H, __half* L, size_t idx,
                                            float v0, float v1) {
    __half h0 = __float2half_rn(v0), h1 = __float2half_rn(v1);
    *(__half2*)(H + idx) = __halves2half2(h0, h1);
    *(__half2*)(L + idx) = __halves2half2(__float2half_rn(v0 - __half2float(h0)),
                                          __float2half_rn(v1 - __half2float(h1)));
}

// ---------------- conversions ----------------
__global__ __launch_bounds__(256) void splitx(const float* __restrict__ in,
                                              __half* __restrict__ hi,
                                              __half* __restrict__ lo, int n4)
{
    int i = blockIdx.x * 256 + threadIdx.x;
    if (i >= n4) return;
    float4 v = ((const float4*)in)[i];
    float vv[4] = {v.x, v.y, v.z, v.w};
    __half h[4], l[4];
    #pragma unroll
    for (int k = 0; k < 4; k++) {
        h[k] = __float2half_rn(vv[k]);
        l[k] = __float2half_rn(vv[k] - __half2float(h[k]));
    }
    *(__half2*)(hi + 4 * (size_t)i)     = __halves2half2(h[0], h[1]);
    *(__half2*)(hi + 4 * (size_t)i + 2) = __halves2half2(h[2], h[3]);
    *(__half2*)(lo + 4 * (size_t)i)     = __halves2half2(l[0], l[1]);
    *(__half2*)(lo + 4 * (size_t)i + 2) = __halves2half2(l[2], l[3]);
}

// W[K][N] -> Wt[N][K] fp16; blockIdx.z selects which of 4 weights
__global__ void wT16(const float* w0, const float* w1, const float* w2,
                     const float* w3, __half* __restrict__ dst)
{
    const float* W = (blockIdx.z == 0) ? w0 : (blockIdx.z == 1) ? w1
                   : (blockIdx.z == 2) ? w2 : w3;
    __half* Wt = dst + (size_t)blockIdx.z * D_MODEL * D_MODEL;
    __shared__ float t[32][33];
    int tx = threadIdx.x, ty = threadIdx.y;
    int n0 = blockIdx.x * 32, k0 = blockIdx.y * 32;
    #pragma unroll
    for (int j = 0; j < 32; j += 8)
        t[ty + j][tx] = W[(size_t)(k0 + ty + j) * D_MODEL + n0 + tx];
    __syncthreads();
    #pragma unroll
    for (int j = 0; j < 32; j += 8)
        Wt[(size_t)(n0 + ty + j) * D_MODEL + k0 + tx] = __float2half_rn(t[tx][ty + j]);
}

// ---------------- GEMM: (Ah+Al)[M,K] @ B[N,K]^T + bias ----------------
#define TKk 32
#define NKT (D_MODEL / TKk)
#define RSTR 80
#define TILEB (128 * RSTR)
#define STAGEB (3 * TILEB)
#define GEMM_SMEM (2 * STAGEB)

__device__ __forceinline__ void load_stage(
    uint32_t base, const __half* __restrict__ Ah, const __half* __restrict__ Al,
    const __half* __restrict__ Bw, int m0, int n0, int k0, int tid)
{
    #pragma unroll
    for (int it = 0; it < 2; it++) {
        const int idx = tid + it * 256;
        const int r = idx >> 2;
        const int c = idx & 3;
        const uint32_t so = (uint32_t)(r * RSTR + c * 16);
        const size_t ga = (size_t)(m0 + r) * D_MODEL + k0 + c * 8;
        const size_t gb = (size_t)(n0 + r) * D_MODEL + k0 + c * 8;
        CP_ASYNC16(base + so,             Ah + ga);
        CP_ASYNC16(base + TILEB + so,     Al + ga);
        CP_ASYNC16(base + 2 * TILEB + so, Bw + gb);
    }
}

__global__ __launch_bounds__(256) void gemm_hmma(
    const __half* __restrict__ Ah, const __half* __restrict__ Al,
    const __half* __restrict__ Bw, const float* __restrict__ bias,
    int mode, void* o1, void* o2)
{
    extern __shared__ char sm[];
    const uint32_t smb = smem_u32(sm);
    const int tid = threadIdx.x;
    const int wid = tid >> 5;
    const int lane = tid & 31;
    const int warp_m = wid & 1;
    const int warp_n = wid >> 1;
    const int m0 = blockIdx.y * 128;
    const int n0 = blockIdx.x * 128;
    const int lrow = lane & 15;
    const uint32_t lcol = (uint32_t)((lane >> 4) * 16);

    float acc[4][4][4];
    #pragma unroll
    for (int i = 0; i < 4; i++)
        #pragma unroll
        for (int j = 0; j < 4; j++)
            #pragma unroll
            for (int r = 0; r < 4; r++) acc[i][j][r] = 0.f;

    load_stage(smb, Ah, Al, Bw, m0, n0, 0, tid);
    CP_COMMIT();

    for (int kt = 0; kt < NKT; kt++) {
        if (kt + 1 < NKT) {
            load_stage(smb + (uint32_t)(((kt + 1) & 1) * STAGEB),
                       Ah, Al, Bw, m0, n0, (kt + 1) * TKk, tid);
            CP_COMMIT();
            CP_WAIT(1);
        } else {
            CP_WAIT(0);
        }
        __syncthreads();
        const uint32_t st = smb + (uint32_t)((kt & 1) * STAGEB);

        #pragma unroll
        for (int ks = 0; ks < 2; ks++) {
            const uint32_t ko = (uint32_t)(ks * 32) + lcol;
            uint32_t b[2][4], a[4][4];
            #pragma unroll
            for (int p = 0; p < 2; p++)
                LDMX4(b[p][0], b[p][1], b[p][2], b[p][3],
                      st + 2 * TILEB + (uint32_t)((warp_n * 32 + p * 16 + lrow) * RSTR) + ko);
            #pragma unroll
            for (int mi = 0; mi < 4; mi++)
                LDMX4(a[mi][0], a[mi][1], a[mi][2], a[mi][3],
                      st + (uint32_t)((warp_m * 64 + mi * 16 + lrow) * RSTR) + ko);
            #pragma unroll
            for (int mi = 0; mi < 4; mi++)
                #pragma unroll
                for (int ni = 0; ni < 4; ni++)
                    MMA16816(acc[mi][ni], a[mi][0], a[mi][1], a[mi][2], a[mi][3],
                             b[ni >> 1][ni & 1], b[ni >> 1][2 + (ni & 1)]);
            #pragma unroll
            for (int mi = 0; mi < 4; mi++)
                LDMX4(a[mi][0], a[mi][1], a[mi][2], a[mi][3],
                      st + TILEB + (uint32_t)((warp_m * 64 + mi * 16 + lrow) * RSTR) + ko);
            #pragma unroll
            for (int mi = 0; mi < 4; mi++)
                #pragma unroll
                for (int ni = 0; ni < 4; ni++)
                    MMA16816(acc[mi][ni], a[mi][0], a[mi][1], a[mi][2], a[mi][3],
                             b[ni >> 1][ni & 1], b[ni >> 1][2 + (ni & 1)]);
        }
        __syncthreads();
    }

    const int g = lane >> 2;
    const int t = lane & 3;
    #pragma unroll
    for (int mi = 0; mi < 4; mi++) {
        #pragma unroll
        for (int ni = 0; ni < 4; ni++) {
            const int n = n0 + warp_n * 32 + ni * 8 + t * 2;
            const float b0 = bias[n], b1 = bias[n + 1];
            #pragma unroll
            for (int hf = 0; hf < 2; hf++) {
                const int m = m0 + warp_m * 64 + mi * 16 + g + hf * 8;
                const float v0 = acc[mi][ni][hf * 2 + 0] + b0;
                const float v1 = acc[mi][ni][hf * 2 + 1] + b1;
                if (mode == 0) {
                    *(float2*)((float*)o1 + (size_t)m * D_MODEL + n) = make_float2(v0, v1);
                } else {
                    const int bb = m >> 11, tt = m & (SEQ - 1);
                    const int hh = n >> 6, dd = n & (DK - 1);
                    if (mode == 1) {
                        split_store((__half*)o1, (__half*)o2,
                                    ((size_t)(bb * 16 + hh) * SEQ + tt) * DK + dd,
                                    v0 * 0.125f, v1 * 0.125f);
                    } else if (mode == 2) {
                        *(__half2*)((__half*)o1 + ((size_t)(bb * 16 + hh) * SEQ + tt) * DK + dd)
                            = __floats2half2_rn(v0, v1);
                    } else {
                        const size_t idx = ((size_t)(bb * 16 + hh) * DK + dd) * SEQ + tt;
                        ((__half*)o1)[idx]       = __float2half_rn(v0);
                        ((__half*)o1)[idx + SEQ] = __float2half_rn(v1);
                    }
                }
            }
        }
    }
}

// ---------------- FlashAttention-2 on HMMA ----------------
#define BQ 128
#define BKV 64
#define ASTR 144                 // bytes per row: 64 halves + 8 pad
#define QTILE (BQ * ASTR)
#define KVTILE (BKV * ASTR)
#define KVBUF (2 * KVTILE)
#define ATTN_SMEM (2 * QTILE + 2 * KVBUF)   // 73728

__device__ __forceinline__ void attn_load_kv(
    uint32_t base, const __half* __restrict__ Kg, const __half* __restrict__ Vtg,
    size_t bhoff, int k0, int tid)
{
    #pragma unroll
    for (int it = 0; it < 2; it++) {
        const int i = tid + it * 256;
        const int r = i >> 3;
        const int c = i & 7;
        const uint32_t so = (uint32_t)(r * ASTR + c * 16);
        CP_ASYNC16(base + so,          Kg  + bhoff + (size_t)(k0 + r) * DK + c * 8);
        CP_ASYNC16(base + KVTILE + so, Vtg + bhoff + (size_t)r * SEQ + k0 + c * 8);
    }
}

__global__ __launch_bounds__(256) void attn_hmma(
    const __half* __restrict__ Qh, const __half* __restrict__ Ql,
    const __half* __restrict__ Kg, const __half* __restrict__ Vtg,
    __half* __restrict__ Oh, __half* __restrict__ Ol)
{
    extern __shared__ char sm[];
    const uint32_t smb = smem_u32(sm);
    const int tid = threadIdx.x;
    const int wid = tid >> 5;
    const int lane = tid & 31;
    const int qb = gridDim.x - 1 - blockIdx.x;     // heavy CTAs first
    const int bh = blockIdx.y;
    const int q0 = qb * BQ;
    const size_t bhoff = (size_t)bh * SEQ * DK;
    const int lrow = lane & 15;
    const uint32_t lcol = (uint32_t)((lane >> 4) * 16);
    const int g = lane >> 2;
    const int t = lane & 3;
    const int q0w = q0 + wid * 16;
    const uint32_t kvb = smb + 2 * QTILE;

    // load Q hi/lo
    #pragma unroll
    for (int it = 0; it < 4; it++) {
        const int i = tid + it * 256;
        const int r = i >> 3;
        const int c = i & 7;
        const uint32_t so = (uint32_t)(r * ASTR + c * 16);
        CP_ASYNC16(smb + so,         Qh + bhoff + (size_t)(q0 + r) * DK + c * 8);
        CP_ASYNC16(smb + QTILE + so, Ql + bhoff + (size_t)(q0 + r) * DK + c * 8);
    }
    attn_load_kv(kvb, Kg, Vtg, bhoff, 0, tid);
    CP_COMMIT();
    CP_WAIT(0);
    __syncthreads();

    // preload Q fragments
    uint32_t qhf[4][4], qlf[4][4];
    #pragma unroll
    for (int kf = 0; kf < 4; kf++) {
        const uint32_t ro = (uint32_t)((wid * 16 + lrow) * ASTR) + (uint32_t)(kf * 32) + lcol;
        LDMX4(qhf[kf][0], qhf[kf][1], qhf[kf][2], qhf[kf][3], smb + ro);
        LDMX4(qlf[kf][0], qlf[kf][1], qlf[kf][2], qlf[kf][3], smb + QTILE + ro);
    }

    float oacc[8][4];
    #pragma unroll
    for (int f = 0; f < 8; f++)
        #pragma unroll
        for (int r = 0; r < 4; r++) oacc[f][r] = 0.f;
    float m_i[2] = {-1e30f, -1e30f};
    float l_i[2] = {0.f, 0.f};

    const int nt = qb * 2 + 2;
    for (int kt = 0; kt < nt; kt++) {
        const int k0 = kt * BKV;
        if (kt + 1 < nt) {
            attn_load_kv(kvb + (uint32_t)(((kt + 1) & 1) * KVBUF), Kg, Vtg, bhoff, k0 + BKV, tid);
            CP_COMMIT();
        }

        if (q0w + 15 >= k0) {
            const uint32_t kb = kvb + (uint32_t)((kt & 1) * KVBUF);
            const uint32_t vb = kb + KVTILE;

            float s[8][4];
            #pragma unroll
            for (int f = 0; f < 8; f++)
                #pragma unroll
                for (int r = 0; r < 4; r++) s[f][r] = 0.f;

            #pragma unroll
            for (int kf = 0; kf < 4; kf++) {
                const uint32_t ko = (uint32_t)(kf * 32) + lcol;
                #pragma unroll
                for (int p = 0; p < 4; p++) {
                    uint32_t b0, b1, b2, b3;
                    LDMX4(b0, b1, b2, b3, kb + (uint32_t)((p * 16 + lrow) * ASTR) + ko);
                    MMA16816(s[2*p],   qhf[kf][0], qhf[kf][1], qhf[kf][2], qhf[kf][3], b0, b2);
                    MMA16816(s[2*p],   qlf[kf][0], qlf[kf][1], qlf[kf][2], qlf[kf][3], b0, b2);
                    MMA16816(s[2*p+1], qhf[kf][0], qhf[kf][1], qhf[kf][2], qhf[kf][3], b1, b3);
                    MMA16816(s[2*p+1], qlf[kf][0], qlf[kf][1], qlf[kf][2], qlf[kf][3], b1, b3);
                }
            }

            // causal mask (diag tiles only)
            if (k0 + 63 > q0w) {
                const int r0 = q0w + g, r1 = r0 + 8;
                #pragma unroll
                for (int ni = 0; ni < 8; ni++) {
                    const int c0 = k0 + ni * 8 + t * 2;
                    if (c0     > r0) s[ni][0] = -1e30f;
                    if (c0 + 1 > r0) s[ni][1] = -1e30f;
                    if (c0     > r1) s[ni][2] = -1e30f;
                    if (c0 + 1 > r1) s[ni][3] = -1e30f;
                }
            }

            // online softmax
            float rmx0 = -1e30f, rmx1 = -1e30f;
            #pragma unroll
            for (int ni = 0; ni < 8; ni++) {
                rmx0 = fmaxf(rmx0, fmaxf(s[ni][0], s[ni][1]));
                rmx1 = fmaxf(rmx1, fmaxf(s[ni][2], s[ni][3]));
            }
            rmx0 = fmaxf(rmx0, __shfl_xor_sync(0xffffffffu, rmx0, 1));
            rmx0 = fmaxf(rmx0, __shfl_xor_sync(0xffffffffu, rmx0, 2));
            rmx1 = fmaxf(rmx1, __shfl_xor_sync(0xffffffffu, rmx1, 1));
            rmx1 = fmaxf(rmx1, __shfl_xor_sync(0xffffffffu, rmx1, 2));
            const float mn0 = fmaxf(m_i[0], rmx0);
            const float mn1 = fmaxf(m_i[1], rmx1);
            const float sc0 = __expf(m_i[0] - mn0);
            const float sc1 = __expf(m_i[1] - mn1);
            float rs0 = 0.f, rs1 = 0.f;
            #pragma unroll
            for (int ni = 0; ni < 8; ni++) {
                s[ni][0] = __expf(s[ni][0] - mn0); rs0 += s[ni][0];
                s[ni][1] = __expf(s[ni][1] - mn0); rs0 += s[ni][1];
                s[ni][2] = __expf(s[ni][2] - mn1); rs1 += s[ni][2];
                s[ni][3] = __expf(s[ni][3] - mn1); rs1 += s[ni][3];
            }
            rs0 += __shfl_xor_sync(0xffffffffu, rs0, 1);
            rs0 += __shfl_xor_sync(0xffffffffu, rs0, 2);
            rs1 += __shfl_xor_sync(0xffffffffu, rs1, 1);
            rs1 += __shfl_xor_sync(0xffffffffu, rs1, 2);
            m_i[0] = mn0; m_i[1] = mn1;
            l_i[0] = l_i[0] * sc0 + rs0;
            l_i[1] = l_i[1] * sc1 + rs1;
            #pragma unroll
            for (int f = 0; f < 8; f++) {
                oacc[f][0] *= sc0; oacc[f][1] *= sc0;
                oacc[f][2] *= sc1; oacc[f][3] *= sc1;
            }

            // PV: P frags straight from s regs
            #pragma unroll
            for (int kf = 0; kf < 4; kf++) {
                const uint32_t pa0 = packh2(s[2*kf][0],   s[2*kf][1]);
                const uint32_t pa1 = packh2(s[2*kf][2],   s[2*kf][3]);
                const uint32_t pa2 = packh2(s[2*kf+1][0], s[2*kf+1][1]);
                const uint32_t pa3 = packh2(s[2*kf+1][2], s[2*kf+1][3]);
                const uint32_t ko = (uint32_t)(kf * 32) + lcol;
                #pragma unroll
                for (int p = 0; p < 4; p++) {
                    uint32_t b0, b1, b2, b3;
                    LDMX4(b0, b1, b2, b3, vb + (uint32_t)((p * 16 + lrow) * ASTR) + ko);
                    MMA16816(oacc[2*p],   pa0, pa1, pa2, pa3, b0, b2);
                    MMA16816(oacc[2*p+1], pa0, pa1, pa2, pa3, b1, b3);
                }
            }
        }
        CP_WAIT(0);
        __syncthreads();
    }

    // epilogue
    const float inv0 = 1.0f / l_i[0];
    const float inv1 = 1.0f / l_i[1];
    const int b = bh >> 4, h = bh & 15;
    const int r0 = q0w + g, r1 = r0 + 8;
    #pragma unroll
    for (int ni = 0; ni < 8; ni++) {
        const int col = h * 64 + ni * 8 + t * 2;
        split_store(Oh, Ol, (size_t)(b * SEQ + r0) * D_MODEL + col,
                    oacc[ni][0] * inv0, oacc[ni][1] * inv0);
        split_store(Oh, Ol, (size_t)(b * SEQ + r1) * D_MODEL + col,
                    oacc[ni][2] * inv1, oacc[ni][3] * inv1);
    }
}

// ---------------------------------------------------------------------------
extern "C" void kernel_launch(void* const* d_in, const int* in_sizes, int n_in,
                              void* d_out, int out_size)
{
    const float* x   = (const float*)d_in[0];
    const float* w_q = (const float*)d_in[2];
    const float* b_q = (const float*)d_in[3];
    const float* w_k = (const float*)d_in[4];
    const float* b_k = (const float*)d_in[5];
    const float* w_v = (const float*)d_in[6];
    const float* b_v = (const float*)d_in[7];
    const float* w_o = (const float*)d_in[8];
    const float* b_o = (const float*)d_in[9];
    float* out = (float*)d_out;

    __half *xh, *xl, *w4, *qh, *ql, *kk, *vt, *oh, *ol;
    cudaGetSymbolAddress((void**)&xh, g_xh);
    cudaGetSymbolAddress((void**)&xl, g_xl);
    cudaGetSymbolAddress((void**)&w4, g_w4);
    cudaGetSymbolAddress((void**)&qh, g_qh);
    cudaGetSymbolAddress((void**)&ql, g_ql);
    cudaGetSymbolAddress((void**)&kk, g_k);
    cudaGetSymbolAddress((void**)&vt, g_vt);
    cudaGetSymbolAddress((void**)&oh, g_oh);
    cudaGetSymbolAddress((void**)&ol, g_ol);

    const size_t WSZ = (size_t)D_MODEL * D_MODEL;
    __half *wq = w4, *wk = w4 + WSZ, *wv = w4 + 2 * WSZ, *wo = w4 + 3 * WSZ;

    cudaFuncSetAttribute(gemm_hmma, cudaFuncAttributeMaxDynamicSharedMemorySize, GEMM_SMEM);
    cudaFuncSetAttribute(attn_hmma, cudaFuncAttributeMaxDynamicSharedMemorySize, ATTN_SMEM);

    const int n4 = M_ROWS * D_MODEL / 4;
    splitx<<<(n4 + 255) / 256, 256>>>(x, xh, xl, n4);
    wT16<<<dim3(D_MODEL / 32, D_MODEL / 32, 4), dim3(32, 8)>>>(w_q, w_k, w_v, w_o, w4);

    dim3 gg(D_MODEL / 128, M_ROWS / 128);
    gemm_hmma<<<gg, 256, GEMM_SMEM>>>(xh, xl, wq, b_q, 1, qh, ql);
    gemm_hmma<<<gg, 256, GEMM_SMEM>>>(xh, xl, wk, b_k, 2, kk, nullptr);
    gemm_hmma<<<gg, 256, GEMM_SMEM>>>(xh, xl, wv, b_v, 3, vt, nullptr);

    attn_hmma<<<dim3(SEQ / BQ, 64), 256, ATTN_SMEM>>>(qh, ql, kk, vt, oh, ol);

    gemm_hmma<<<gg, 256, GEMM_SMEM>>>(oh, ol, wo, b_o, 0, out, nullptr);
}

// round 6
// speedup vs baseline: 4.1045x; 1.0023x over previous
#include <cuda_runtime.h>
#include <cuda_fp16.h>
#include <cstdint>
#include <cstddef>

#define D_MODEL 1024
#define N_HEADS 16
#define BATCH   4
#define SEQ     2048
#define DK      64
#define M_ROWS  (BATCH * SEQ)
#define BHT     (64 * SEQ * DK)

__device__ __half g_xh[M_ROWS * D_MODEL];
__device__ __half g_xl[M_ROWS * D_MODEL];
__device__ __half g_w4[4 * D_MODEL * D_MODEL];
__device__ __half g_qh[BHT];
__device__ __half g_ql[BHT];
__device__ __half g_k [BHT];
__device__ __half g_vt[BHT];            // [bh][dk][t]
__device__ __half g_oh[M_ROWS * D_MODEL];
__device__ __half g_ol[M_ROWS * D_MODEL];

__device__ __forceinline__ uint32_t smem_u32(const void* p) {
    uint32_t a;
    asm("{ .reg .u64 t; cvta.to.shared.u64 t, %1; cvt.u32.u64 %0, t; }" : "=r"(a) : "l"(p));
    return a;
}
#define CP_ASYNC16(dst, src) \
    asm volatile("cp.async.cg.shared.global [%0], [%1], 16;" :: "r"(dst), "l"(src))
#define CP_COMMIT()  asm volatile("cp.async.commit_group;" ::: "memory")
#define CP_WAIT(n)   asm volatile("cp.async.wait_group %0;" :: "n"(n) : "memory")
#define LDMX4(r0, r1, r2, r3, addr) \
    asm volatile("ldmatrix.sync.aligned.m8n8.x4.shared.b16 {%0,%1,%2,%3}, [%4];" \
        : "=r"(r0), "=r"(r1), "=r"(r2), "=r"(r3) : "r"(addr))
#define MMA16816(acc, a0, a1, a2, a3, b0, b1) \
    asm volatile("mma.sync.aligned.m16n8k16.row.col.f32.f16.f16.f32 " \
        "{%0,%1,%2,%3},{%4,%5,%6,%7},{%8,%9},{%0,%1,%2,%3};" \
        : "+f"((acc)[0]), "+f"((acc)[1]), "+f"((acc)[2]), "+f"((acc)[3]) \
        : "r"(a0), "r"(a1), "r"(a2), "r"(a3), "r"(b0), "r"(b1))

__device__ __forceinline__ uint32_t packh2(float x, float y) {
    __half2 h = __floats2half2_rn(x, y);
    return *(uint32_t*)&h;
}
__device__ __forceinline__ void split_store(__half* H, __half* L, size_t idx,
                                            float v0, float v1) {
    __half h0 = __float2half_rn(v0), h1 = __float2half_rn(v1);
    *(__half2*)(H + idx) = __halves2half2(h0, h1);
    *(__half2*)(L + idx) = __halves2half2(__float2half_rn(v0 - __half2float(h0)),
                                          __float2half_rn(v1 - __half2float(h1)));
}

// ---------------- conversions ----------------
__global__ __launch_bounds__(256) void splitx(const float* __restrict__ in,
                                              __half* __restrict__ hi,
                                              __half* __restrict__ lo, int n4)
{
    int i = blockIdx.x * 256 + threadIdx.x;
    if (i >= n4) return;
    float4 v = ((const float4*)in)[i];
    float vv[4] = {v.x, v.y, v.z, v.w};
    __half h[4], l[4];
    #pragma unroll
    for (int k = 0; k < 4; k++) {
        h[k] = __float2half_rn(vv[k]);
        l[k] = __float2half_rn(vv[k] - __half2float(h[k]));
    }
    *(__half2*)(hi + 4 * (size_t)i)     = __halves2half2(h[0], h[1]);
    *(__half2*)(hi + 4 * (size_t)i + 2) = __halves2half2(h[2], h[3]);
    *(__half2*)(lo + 4 * (size_t)i)     = __halves2half2(l[0], l[1]);
    *(__half2*)(lo + 4 * (size_t)i + 2) = __halves2half2(l[2], l[3]);
}

// W[K][N] -> Wt[N][K] fp16; blockIdx.z selects which of 4 weights
__global__ void wT16(const float* w0, const float* w1, const float* w2,
                     const float* w3, __half* __restrict__ dst)
{
    const float* W = (blockIdx.z == 0) ? w0 : (blockIdx.z == 1) ? w1
                   : (blockIdx.z == 2) ? w2 : w3;
    __half* Wt = dst + (size_t)blockIdx.z * D_MODEL * D_MODEL;
    __shared__ float t[32][33];
    int tx = threadIdx.x, ty = threadIdx.y;
    int n0 = blockIdx.x * 32, k0 = blockIdx.y * 32;
    #pragma unroll
    for (int j = 0; j < 32; j += 8)
        t[ty + j][tx] = W[(size_t)(k0 + ty + j) * D_MODEL + n0 + tx];
    __syncthreads();
    #pragma unroll
    for (int j = 0; j < 32; j += 8)
        Wt[(size_t)(n0 + ty + j) * D_MODEL + k0 + tx] = __float2half_rn(t[tx][ty + j]);
}

// ---------------- GEMM: (Ah+Al)[M,K] @ B[N,K]^T + bias ----------------
#define TKk 32
#define NKT (D_MODEL / TKk)
#define RSTR 80
#define TILEB (128 * RSTR)
#define STAGEB (3 * TILEB)          // Ah, Al, B tiles
#define NSTAGE 3
#define GEMM_SMEM (NSTAGE * STAGEB) // 92160

__device__ __forceinline__ void load_stage(
    uint32_t base, const __half* __restrict__ Ah, const __half* __restrict__ Al,
    const __half* __restrict__ Bw, int m0, int n0, int k0, int tid)
{
    #pragma unroll
    for (int it = 0; it < 2; it++) {
        const int idx = tid + it * 256;
        const int r = idx >> 2;
        const int c = idx & 3;
        const uint32_t so = (uint32_t)(r * RSTR + c * 16);
        const size_t ga = (size_t)(m0 + r) * D_MODEL + k0 + c * 8;
        const size_t gb = (size_t)(n0 + r) * D_MODEL + k0 + c * 8;
        CP_ASYNC16(base + so,             Ah + ga);
        CP_ASYNC16(base + TILEB + so,     Al + ga);
        CP_ASYNC16(base + 2 * TILEB + so, Bw + gb);
    }
}

__global__ __launch_bounds__(256) void gemm_hmma(
    const __half* __restrict__ Ah, const __half* __restrict__ Al,
    const __half* __restrict__ Bw, const float* __restrict__ bias,
    int mode, void* o1, void* o2)
{
    extern __shared__ char sm[];
    const uint32_t smb = smem_u32(sm);
    const int tid = threadIdx.x;
    const int wid = tid >> 5;
    const int lane = tid & 31;
    const int warp_m = wid & 1;
    const int warp_n = wid >> 1;
    const int m0 = blockIdx.y * 128;
    const int n0 = blockIdx.x * 128;
    const int lrow = lane & 15;
    const uint32_t lcol = (uint32_t)((lane >> 4) * 16);

    float acc[4][4][4];
    #pragma unroll
    for (int i = 0; i < 4; i++)
        #pragma unroll
        for (int j = 0; j < 4; j++)
            #pragma unroll
            for (int r = 0; r < 4; r++) acc[i][j][r] = 0.f;

    load_stage(smb,          Ah, Al, Bw, m0, n0, 0,   tid); CP_COMMIT();
    load_stage(smb + STAGEB, Ah, Al, Bw, m0, n0, TKk, tid); CP_COMMIT();

    int stage = 0;
    for (int kt = 0; kt < NKT; kt++) {
        CP_WAIT(1);                  // ordered: all but newest group done -> stage kt ready
        __syncthreads();             // also: everyone done reading the buffer we reload below

        if (kt + 2 < NKT) {
            int ns = stage + 2; if (ns >= NSTAGE) ns -= NSTAGE;
            load_stage(smb + (uint32_t)(ns * STAGEB), Ah, Al, Bw, m0, n0, (kt + 2) * TKk, tid);
        }
        CP_COMMIT();                 // unconditional: keeps group-count semantics valid at tail

        const uint32_t st = smb + (uint32_t)(stage * STAGEB);
        #pragma unroll
        for (int ks = 0; ks < 2; ks++) {
            const uint32_t ko = (uint32_t)(ks * 32) + lcol;
            uint32_t b[2][4], a[4][4];
            #pragma unroll
            for (int p = 0; p < 2; p++)
                LDMX4(b[p][0], b[p][1], b[p][2], b[p][3],
                      st + 2 * TILEB + (uint32_t)((warp_n * 32 + p * 16 + lrow) * RSTR) + ko);
            #pragma unroll
            for (int mi = 0; mi < 4; mi++)
                LDMX4(a[mi][0], a[mi][1], a[mi][2], a[mi][3],
                      st + (uint32_t)((warp_m * 64 + mi * 16 + lrow) * RSTR) + ko);
            #pragma unroll
            for (int mi = 0; mi < 4; mi++)
                #pragma unroll
                for (int ni = 0; ni < 4; ni++)
                    MMA16816(acc[mi][ni], a[mi][0], a[mi][1], a[mi][2], a[mi][3],
                             b[ni >> 1][ni & 1], b[ni >> 1][2 + (ni & 1)]);
            #pragma unroll
            for (int mi = 0; mi < 4; mi++)
                LDMX4(a[mi][0], a[mi][1], a[mi][2], a[mi][3],
                      st + TILEB + (uint32_t)((warp_m * 64 + mi * 16 + lrow) * RSTR) + ko);
            #pragma unroll
            for (int mi = 0; mi < 4; mi++)
                #pragma unroll
                for (int ni = 0; ni < 4; ni++)
                    MMA16816(acc[mi][ni], a[mi][0], a[mi][1], a[mi][2], a[mi][3],
                             b[ni >> 1][ni & 1], b[ni >> 1][2 + (ni & 1)]);
        }
        if (++stage >= NSTAGE) stage = 0;
    }

    const int g = lane >> 2;
    const int t = lane & 3;
    #pragma unroll
    for (int mi = 0; mi < 4; mi++) {
        #pragma unroll
        for (int ni = 0; ni < 4; ni++) {
            const int n = n0 + warp_n * 32 + ni * 8 + t * 2;
            const float b0 = bias[n], b1 = bias[n + 1];
            #pragma unroll
            for (int hf = 0; hf < 2; hf++) {
                const int m = m0 + warp_m * 64 + mi * 16 + g + hf * 8;
                const float v0 = acc[mi][ni][hf * 2 + 0] + b0;
                const float v1 = acc[mi][ni][hf * 2 + 1] + b1;
                if (mode == 0) {
                    *(float2*)((float*)o1 + (size_t)m * D_MODEL + n) = make_float2(v0, v1);
                } else {
                    const int bb = m >> 11, tt = m & (SEQ - 1);
                    const int hh = n >> 6, dd = n & (DK - 1);
                    if (mode == 1) {
                        split_store((__half*)o1, (__half*)o2,
                                    ((size_t)(bb * 16 + hh) * SEQ + tt) * DK + dd,
                                    v0 * 0.125f, v1 * 0.125f);
                    } else if (mode == 2) {
                        *(__half2*)((__half*)o1 + ((size_t)(bb * 16 + hh) * SEQ + tt) * DK + dd)
                            = __floats2half2_rn(v0, v1);
                    } else {
                        const size_t idx = ((size_t)(bb * 16 + hh) * DK + dd) * SEQ + tt;
                        ((__half*)o1)[idx]       = __float2half_rn(v0);
                        ((__half*)o1)[idx + SEQ] = __float2half_rn(v1);
                    }
                }
            }
        }
    }
}

// ---------------- FlashAttention-2 on HMMA ----------------
#define BQ 128
#define BKV 64
#define ASTR 144
#define QTILE (BQ * ASTR)
#define KVTILE (BKV * ASTR)
#define KVBUF (2 * KVTILE)
#define ATTN_SMEM (2 * QTILE + 2 * KVBUF)   // 73728

__device__ __forceinline__ void attn_load_kv(
    uint32_t base, const __half* __restrict__ Kg, const __half* __restrict__ Vtg,
    size_t bhoff, int k0, int tid)
{
    #pragma unroll
    for (int it = 0; it < 2; it++) {
        const int i = tid + it * 256;
        const int r = i >> 3;
        const int c = i & 7;
        const uint32_t so = (uint32_t)(r * ASTR + c * 16);
        CP_ASYNC16(base + so,          Kg  + bhoff + (size_t)(k0 + r) * DK + c * 8);
        CP_ASYNC16(base + KVTILE + so, Vtg + bhoff + (size_t)r * SEQ + k0 + c * 8);
    }
}

__global__ __launch_bounds__(256) void attn_hmma(
    const __half* __restrict__ Qh, const __half* __restrict__ Ql,
    const __half* __restrict__ Kg, const __half* __restrict__ Vtg,
    __half* __restrict__ Oh, __half* __restrict__ Ol)
{
    extern __shared__ char sm[];
    const uint32_t smb = smem_u32(sm);
    const int tid = threadIdx.x;
    const int wid = tid >> 5;
    const int lane = tid & 31;
    const int qb = gridDim.x - 1 - blockIdx.x;
    const int bh = blockIdx.y;
    const int q0 = qb * BQ;
    const size_t bhoff = (size_t)bh * SEQ * DK;
    const int lrow = lane & 15;
    const uint32_t lcol = (uint32_t)((lane >> 4) * 16);
    const int g = lane >> 2;
    const int t = lane & 3;
    const int q0w = q0 + wid * 16;
    const uint32_t kvb = smb + 2 * QTILE;

    #pragma unroll
    for (int it = 0; it < 4; it++) {
        const int i = tid + it * 256;
        const int r = i >> 3;
        const int c = i & 7;
        const uint32_t so = (uint32_t)(r * ASTR + c * 16);
        CP_ASYNC16(smb + so,         Qh + bhoff + (size_t)(q0 + r) * DK + c * 8);
        CP_ASYNC16(smb + QTILE + so, Ql + bhoff + (size_t)(q0 + r) * DK + c * 8);
    }
    attn_load_kv(kvb, Kg, Vtg, bhoff, 0, tid);
    CP_COMMIT();
    CP_WAIT(0);
    __syncthreads();

    uint32_t qhf[4][4], qlf[4][4];
    #pragma unroll
    for (int kf = 0; kf < 4; kf++) {
        const uint32_t ro = (uint32_t)((wid * 16 + lrow) * ASTR) + (uint32_t)(kf * 32) + lcol;
        LDMX4(qhf[kf][0], qhf[kf][1], qhf[kf][2], qhf[kf][3], smb + ro);
        LDMX4(qlf[kf][0], qlf[kf][1], qlf[kf][2], qlf[kf][3], smb + QTILE + ro);
    }

    float oacc[8][4];
    #pragma unroll
    for (int f = 0; f < 8; f++)
        #pragma unroll
        for (int r = 0; r < 4; r++) oacc[f][r] = 0.f;
    float m_i[2] = {-1e30f, -1e30f};
    float l_i[2] = {0.f, 0.f};

    const int nt = qb * 2 + 2;
    for (int kt = 0; kt < nt; kt++) {
        const int k0 = kt * BKV;
        if (kt + 1 < nt) {
            attn_load_kv(kvb + (uint32_t)(((kt + 1) & 1) * KVBUF), Kg, Vtg, bhoff, k0 + BKV, tid);
            CP_COMMIT();
        }

        if (q0w + 15 >= k0) {
            const uint32_t kb = kvb + (uint32_t)((kt & 1) * KVBUF);
            const uint32_t vb = kb + KVTILE;

            float s[8][4];
            #pragma unroll
            for (int f = 0; f < 8; f++)
                #pragma unroll
                for (int r = 0; r < 4; r++) s[f][r] = 0.f;

            #pragma unroll
            for (int kf = 0; kf < 4; kf++) {
                const uint32_t ko = (uint32_t)(kf * 32) + lcol;
                #pragma unroll
                for (int p = 0; p < 4; p++) {
                    uint32_t b0, b1, b2, b3;
                    LDMX4(b0, b1, b2, b3, kb + (uint32_t)((p * 16 + lrow) * ASTR) + ko);
                    MMA16816(s[2*p],   qhf[kf][0], qhf[kf][1], qhf[kf][2], qhf[kf][3], b0, b2);
                    MMA16816(s[2*p],   qlf[kf][0], qlf[kf][1], qlf[kf][2], qlf[kf][3], b0, b2);
                    MMA16816(s[2*p+1], qhf[kf][0], qhf[kf][1], qhf[kf][2], qhf[kf][3], b1, b3);
                    MMA16816(s[2*p+1], qlf[kf][0], qlf[kf][1], qlf[kf][2], qlf[kf][3], b1, b3);
                }
            }

            if (k0 + 63 > q0w) {
                const int r0 = q0w + g, r1 = r0 + 8;
                #pragma unroll
                for (int ni = 0; ni < 8; ni++) {
                    const int c0 = k0 + ni * 8 + t * 2;
                    if (c0     > r0) s[ni][0] = -1e30f;
                    if (c0 + 1 > r0) s[ni][1] = -1e30f;
                    if (c0     > r1) s[ni][2] = -1e30f;
                    if (c0 + 1 > r1) s[ni][3] = -1e30f;
                }
            }

            float rmx0 = -1e30f, rmx1 = -1e30f;
            #pragma unroll
            for (int ni = 0; ni < 8; ni++) {
                rmx0 = fmaxf(rmx0, fmaxf(s[ni][0], s[ni][1]));
                rmx1 = fmaxf(rmx1, fmaxf(s[ni][2], s[ni][3]));
            }
            rmx0 = fmaxf(rmx0, __shfl_xor_sync(0xffffffffu, rmx0, 1));
            rmx0 = fmaxf(rmx0, __shfl_xor_sync(0xffffffffu, rmx0, 2));
            rmx1 = fmaxf(rmx1, __shfl_xor_sync(0xffffffffu, rmx1, 1));
            rmx1 = fmaxf(rmx1, __shfl_xor_sync(0xffffffffu, rmx1, 2));
            const float mn0 = fmaxf(m_i[0], rmx0);
            const float mn1 = fmaxf(m_i[1], rmx1);
            const float sc0 = __expf(m_i[0] - mn0);
            const float sc1 = __expf(m_i[1] - mn1);
            float rs0 = 0.f, rs1 = 0.f;
            #pragma unroll
            for (int ni = 0; ni < 8; ni++) {
                s[ni][0] = __expf(s[ni][0] - mn0); rs0 += s[ni][0];
                s[ni][1] = __expf(s[ni][1] - mn0); rs0 += s[ni][1];
                s[ni][2] = __expf(s[ni][2] - mn1); rs1 += s[ni][2];
                s[ni][3] = __expf(s[ni][3] - mn1); rs1 += s[ni][3];
            }
            rs0 += __shfl_xor_sync(0xffffffffu, rs0, 1);
            rs0 += __shfl_xor_sync(0xffffffffu, rs0, 2);
            rs1 += __shfl_xor_sync(0xffffffffu, rs1, 1);
            rs1 += __shfl_xor_sync(0xffffffffu, rs1, 2);
            m_i[0] = mn0; m_i[1] = mn1;
            l_i[0] = l_i[0] * sc0 + rs0;
            l_i[1] = l_i[1] * sc1 + rs1;
            #pragma unroll
            for (int f = 0; f < 8; f++) {
                oacc[f][0] *= sc0; oacc[f][1] *= sc0;
                oacc[f][2] *= sc1; oacc[f][3] *= sc1;
            }

            #pragma unroll
            for (int kf = 0; kf < 4; kf++) {
                const uint32_t pa0 = packh2(s[2*kf][0],   s[2*kf][1]);
                const uint32_t pa1 = packh2(s[2*kf][2],   s[2*kf][3]);
                const uint32_t pa2 = packh2(s[2*kf+1][0], s[2*kf+1][1]);
                const uint32_t pa3 = packh2(s[2*kf+1][2], s[2*kf+1][3]);
                const uint32_t ko = (uint32_t)(kf * 32) + lcol;
                #pragma unroll
                for (int p = 0; p < 4; p++) {
                    uint32_t b0, b1, b2, b3;
                    LDMX4(b0, b1, b2, b3, vb + (uint32_t)((p * 16 + lrow) * ASTR) + ko);
                    MMA16816(oacc[2*p],   pa0, pa1, pa2, pa3, b0, b2);
                    MMA16816(oacc[2*p+1], pa0, pa1, pa2, pa3, b1, b3);
                }
            }
        }
        CP_WAIT(0);
        __syncthreads();
    }

    const float inv0 = 1.0f / l_i[0];
    const float inv1 = 1.0f / l_i[1];
    const int b = bh >> 4, h = bh & 15;
    const int r0 = q0w + g, r1 = r0 + 8;
    #pragma unroll
    for (int ni = 0; ni < 8; ni++) {
        const int col = h * 64 + ni * 8 + t * 2;
        split_store(Oh, Ol, (size_t)(b * SEQ + r0) * D_MODEL + col,
                    oacc[ni][0] * inv0, oacc[ni][1] * inv0);
        split_store(Oh, Ol, (size_t)(b * SEQ + r1) * D_MODEL + col,
                    oacc[ni][2] * inv1, oacc[ni][3] * inv1);
    }
}

// ---------------------------------------------------------------------------
extern "C" void kernel_launch(void* const* d_in, const int* in_sizes, int n_in,
                              void* d_out, int out_size)
{
    const float* x   = (const float*)d_in[0];
    const float* w_q = (const float*)d_in[2];
    const float* b_q = (const float*)d_in[3];
    const float* w_k = (const float*)d_in[4];
    const float* b_k = (const float*)d_in[5];
    const float* w_v = (const float*)d_in[6];
    const float* b_v = (const float*)d_in[7];
    const float* w_o = (const float*)d_in[8];
    const float* b_o = (const float*)d_in[9];
    float* out = (float*)d_out;

    __half *xh, *xl, *w4, *qh, *ql, *kk, *vt, *oh, *ol;
    cudaGetSymbolAddress((void**)&xh, g_xh);
    cudaGetSymbolAddress((void**)&xl, g_xl);
    cudaGetSymbolAddress((void**)&w4, g_w4);
    cudaGetSymbolAddress((void**)&qh, g_qh);
    cudaGetSymbolAddress((void**)&ql, g_ql);
    cudaGetSymbolAddress((void**)&kk, g_k);
    cudaGetSymbolAddress((void**)&vt, g_vt);
    cudaGetSymbolAddress((void**)&oh, g_oh);
    cudaGetSymbolAddress((void**)&ol, g_ol);

    const size_t WSZ = (size_t)D_MODEL * D_MODEL;
    __half *wq = w4, *wk = w4 + WSZ, *wv = w4 + 2 * WSZ, *wo = w4 + 3 * WSZ;

    cudaFuncSetAttribute(gemm_hmma, cudaFuncAttributeMaxDynamicSharedMemorySize, GEMM_SMEM);
    cudaFuncSetAttribute(attn_hmma, cudaFuncAttributeMaxDynamicSharedMemorySize, ATTN_SMEM);

    const int n4 = M_ROWS * D_MODEL / 4;
    splitx<<<(n4 + 255) / 256, 256>>>(x, xh, xl, n4);
    wT16<<<dim3(D_MODEL / 32, D_MODEL / 32, 4), dim3(32, 8)>>>(w_q, w_k, w_v, w_o, w4);

    dim3 gg(D_MODEL / 128, M_ROWS / 128);
    gemm_hmma<<<gg, 256, GEMM_SMEM>>>(xh, xl, wq, b_q, 1, qh, ql);
    gemm_hmma<<<gg, 256, GEMM_SMEM>>>(xh, xl, wk, b_k, 2, kk, nullptr);
    gemm_hmma<<<gg, 256, GEMM_SMEM>>>(xh, xl, wv, b_v, 3, vt, nullptr);

    attn_hmma<<<dim3(SEQ / BQ, 64), 256, ATTN_SMEM>>>(qh, ql, kk, vt, oh, ol);

    gemm_hmma<<<gg, 256, GEMM_SMEM>>>(oh, ol, wo, b_o, 0, out, nullptr);
}

// round 7
// speedup vs baseline: 7.3190x; 1.7832x over previous
#include <cuda_runtime.h>
#include <cuda_fp16.h>
#include <cstdint>
#include <cstddef>

#define D_MODEL 1024
#define N_HEADS 16
#define BATCH   4
#define SEQ     2048
#define DK      64
#define M_ROWS  (BATCH * SEQ)
#define BHT     (64 * SEQ * DK)

__device__ __half g_x16[M_ROWS * D_MODEL];
__device__ __half g_w4[4 * D_MODEL * D_MODEL];
__device__ __half g_q [BHT];            // [bh][t][dk], pre-scaled by 0.125
__device__ __half g_k [BHT];            // [bh][t][dk]
__device__ __half g_vt[BHT];            // [bh][dk][t]
__device__ __half g_o [M_ROWS * D_MODEL];

__device__ __forceinline__ uint32_t smem_u32(const void* p) {
    uint32_t a;
    asm("{ .reg .u64 t; cvta.to.shared.u64 t, %1; cvt.u32.u64 %0, t; }" : "=r"(a) : "l"(p));
    return a;
}
#define CP_ASYNC16(dst, src) \
    asm volatile("cp.async.cg.shared.global [%0], [%1], 16;" :: "r"(dst), "l"(src))
#define CP_COMMIT()  asm volatile("cp.async.commit_group;" ::: "memory")
#define CP_WAIT(n)   asm volatile("cp.async.wait_group %0;" :: "n"(n) : "memory")
#define LDMX4(r0, r1, r2, r3, addr) \
    asm volatile("ldmatrix.sync.aligned.m8n8.x4.shared.b16 {%0,%1,%2,%3}, [%4];" \
        : "=r"(r0), "=r"(r1), "=r"(r2), "=r"(r3) : "r"(addr))
#define MMA16816(acc, a0, a1, a2, a3, b0, b1) \
    asm volatile("mma.sync.aligned.m16n8k16.row.col.f32.f16.f16.f32 " \
        "{%0,%1,%2,%3},{%4,%5,%6,%7},{%8,%9},{%0,%1,%2,%3};" \
        : "+f"((acc)[0]), "+f"((acc)[1]), "+f"((acc)[2]), "+f"((acc)[3]) \
        : "r"(a0), "r"(a1), "r"(a2), "r"(a3), "r"(b0), "r"(b1))

__device__ __forceinline__ uint32_t packh2(float x, float y) {
    __half2 h = __floats2half2_rn(x, y);
    return *(uint32_t*)&h;
}

// ---------------- conversions ----------------
__global__ __launch_bounds__(256) void cvtx(const float* __restrict__ in,
                                            __half* __restrict__ out, int n4)
{
    int i = blockIdx.x * 256 + threadIdx.x;
    if (i >= n4) return;
    float4 v = ((const float4*)in)[i];
    *(__half2*)(out + 4 * (size_t)i)     = __floats2half2_rn(v.x, v.y);
    *(__half2*)(out + 4 * (size_t)i + 2) = __floats2half2_rn(v.z, v.w);
}

// W[K][N] -> Wt[N][K] fp16; blockIdx.z selects weight
__global__ void wT16(const float* w0, const float* w1, const float* w2,
                     const float* w3, __half* __restrict__ dst)
{
    const float* W = (blockIdx.z == 0) ? w0 : (blockIdx.z == 1) ? w1
                   : (blockIdx.z == 2) ? w2 : w3;
    __half* Wt = dst + (size_t)blockIdx.z * D_MODEL * D_MODEL;
    __shared__ float t[32][33];
    int tx = threadIdx.x, ty = threadIdx.y;
    int n0 = blockIdx.x * 32, k0 = blockIdx.y * 32;
    #pragma unroll
    for (int j = 0; j < 32; j += 8)
        t[ty + j][tx] = W[(size_t)(k0 + ty + j) * D_MODEL + n0 + tx];
    __syncthreads();
    #pragma unroll
    for (int j = 0; j < 32; j += 8)
        Wt[(size_t)(n0 + ty + j) * D_MODEL + k0 + tx] = __float2half_rn(t[tx][ty + j]);
}

// ---------------- single-pass fp16 GEMM: A[M,K] @ B[N,K]^T + bias ----------------
#define TKk 64
#define NKT (D_MODEL / TKk)          // 16
#define RSTR 144                     // bytes per smem row (64 halves + 8 pad)
#define TILEB (128 * RSTR)           // 18432
#define STAGEB (2 * TILEB)           // A + B
#define NSTAGE 3
#define GEMM_SMEM (NSTAGE * STAGEB)  // 110592

__device__ __forceinline__ void load_stage(
    uint32_t base, const __half* __restrict__ A, const __half* __restrict__ B,
    int m0, int n0, int k0, int tid)
{
    #pragma unroll
    for (int it = 0; it < 4; it++) {
        const int idx = tid + it * 256;      // 0..1023
        const int r = idx >> 3;
        const int c = idx & 7;
        const uint32_t so = (uint32_t)(r * RSTR + c * 16);
        CP_ASYNC16(base + so,         A + (size_t)(m0 + r) * D_MODEL + k0 + c * 8);
        CP_ASYNC16(base + TILEB + so, B + (size_t)(n0 + r) * D_MODEL + k0 + c * 8);
    }
}

__global__ __launch_bounds__(256) void gemm_hmma(
    const __half* __restrict__ A, const __half* __restrict__ Bw,
    const float* __restrict__ bias, int mode, void* o1)
{
    extern __shared__ char sm[];
    const uint32_t smb = smem_u32(sm);
    const int tid = threadIdx.x;
    const int wid = tid >> 5;
    const int lane = tid & 31;
    const int warp_m = wid & 1;
    const int warp_n = wid >> 1;
    const int m0 = blockIdx.y * 128;
    const int n0 = blockIdx.x * 128;
    const int lrow = lane & 15;
    const uint32_t lcol = (uint32_t)((lane >> 4) * 16);

    float acc[4][4][4];
    #pragma unroll
    for (int i = 0; i < 4; i++)
        #pragma unroll
        for (int j = 0; j < 4; j++)
            #pragma unroll
            for (int r = 0; r < 4; r++) acc[i][j][r] = 0.f;

    load_stage(smb,          A, Bw, m0, n0, 0,   tid); CP_COMMIT();
    load_stage(smb + STAGEB, A, Bw, m0, n0, TKk, tid); CP_COMMIT();

    int stage = 0;
    for (int kt = 0; kt < NKT; kt++) {
        CP_WAIT(1);
        __syncthreads();
        if (kt + 2 < NKT) {
            int ns = stage + 2; if (ns >= NSTAGE) ns -= NSTAGE;
            load_stage(smb + (uint32_t)(ns * STAGEB), A, Bw, m0, n0, (kt + 2) * TKk, tid);
        }
        CP_COMMIT();

        const uint32_t st = smb + (uint32_t)(stage * STAGEB);
        #pragma unroll
        for (int ks = 0; ks < 4; ks++) {
            const uint32_t ko = (uint32_t)(ks * 32) + lcol;
            uint32_t b[2][4], a[4][4];
            #pragma unroll
            for (int p = 0; p < 2; p++)
                LDMX4(b[p][0], b[p][1], b[p][2], b[p][3],
                      st + TILEB + (uint32_t)((warp_n * 32 + p * 16 + lrow) * RSTR) + ko);
            #pragma unroll
            for (int mi = 0; mi < 4; mi++)
                LDMX4(a[mi][0], a[mi][1], a[mi][2], a[mi][3],
                      st + (uint32_t)((warp_m * 64 + mi * 16 + lrow) * RSTR) + ko);
            #pragma unroll
            for (int mi = 0; mi < 4; mi++)
                #pragma unroll
                for (int ni = 0; ni < 4; ni++)
                    MMA16816(acc[mi][ni], a[mi][0], a[mi][1], a[mi][2], a[mi][3],
                             b[ni >> 1][ni & 1], b[ni >> 1][2 + (ni & 1)]);
        }
        if (++stage >= NSTAGE) stage = 0;
    }

    const int g = lane >> 2;
    const int t = lane & 3;
    #pragma unroll
    for (int mi = 0; mi < 4; mi++) {
        #pragma unroll
        for (int ni = 0; ni < 4; ni++) {
            const int n = n0 + warp_n * 32 + ni * 8 + t * 2;
            const float b0 = bias[n], b1 = bias[n + 1];
            #pragma unroll
            for (int hf = 0; hf < 2; hf++) {
                const int m = m0 + warp_m * 64 + mi * 16 + g + hf * 8;
                const float v0 = acc[mi][ni][hf * 2 + 0] + b0;
                const float v1 = acc[mi][ni][hf * 2 + 1] + b1;
                if (mode == 0) {
                    *(float2*)((float*)o1 + (size_t)m * D_MODEL + n) = make_float2(v0, v1);
                } else {
                    const int bb = m >> 11, tt = m & (SEQ - 1);
                    const int hh = n >> 6, dd = n & (DK - 1);
                    if (mode == 1) {
                        *(__half2*)((__half*)o1 + ((size_t)(bb * 16 + hh) * SEQ + tt) * DK + dd)
                            = __floats2half2_rn(v0 * 0.125f, v1 * 0.125f);
                    } else if (mode == 2) {
                        *(__half2*)((__half*)o1 + ((size_t)(bb * 16 + hh) * SEQ + tt) * DK + dd)
                            = __floats2half2_rn(v0, v1);
                    } else {
                        const size_t idx = ((size_t)(bb * 16 + hh) * DK + dd) * SEQ + tt;
                        ((__half*)o1)[idx]       = __float2half_rn(v0);
                        ((__half*)o1)[idx + SEQ] = __float2half_rn(v1);
                    }
                }
            }
        }
    }
}

// ---------------- FlashAttention-2 on HMMA (single-pass fp16) ----------------
#define BQ 128
#define BKV 64
#define ASTR 144
#define QTILE (BQ * ASTR)
#define KVTILE (BKV * ASTR)
#define KVBUF (2 * KVTILE)
#define ATTN_SMEM (QTILE + 2 * KVBUF)   // 55296

__device__ __forceinline__ void attn_load_kv(
    uint32_t base, const __half* __restrict__ Kg, const __half* __restrict__ Vtg,
    size_t bhoff, int k0, int tid)
{
    #pragma unroll
    for (int it = 0; it < 2; it++) {
        const int i = tid + it * 256;
        const int r = i >> 3;
        const int c = i & 7;
        const uint32_t so = (uint32_t)(r * ASTR + c * 16);
        CP_ASYNC16(base + so,          Kg  + bhoff + (size_t)(k0 + r) * DK + c * 8);
        CP_ASYNC16(base + KVTILE + so, Vtg + bhoff + (size_t)r * SEQ + k0 + c * 8);
    }
}

__global__ __launch_bounds__(256) void attn_hmma(
    const __half* __restrict__ Qg, const __half* __restrict__ Kg,
    const __half* __restrict__ Vtg, __half* __restrict__ Og)
{
    extern __shared__ char sm[];
    const uint32_t smb = smem_u32(sm);
    const int tid = threadIdx.x;
    const int wid = tid >> 5;
    const int lane = tid & 31;
    const int qb = gridDim.x - 1 - blockIdx.x;   // heavy CTAs first
    const int bh = blockIdx.y;
    const int q0 = qb * BQ;
    const size_t bhoff = (size_t)bh * SEQ * DK;
    const int lrow = lane & 15;
    const uint32_t lcol = (uint32_t)((lane >> 4) * 16);
    const int g = lane >> 2;
    const int t = lane & 3;
    const int q0w = q0 + wid * 16;
    const uint32_t kvb = smb + QTILE;

    #pragma unroll
    for (int it = 0; it < 4; it++) {
        const int i = tid + it * 256;
        const int r = i >> 3;
        const int c = i & 7;
        CP_ASYNC16(smb + (uint32_t)(r * ASTR + c * 16),
                   Qg + bhoff + (size_t)(q0 + r) * DK + c * 8);
    }
    attn_load_kv(kvb, Kg, Vtg, bhoff, 0, tid);
    CP_COMMIT();
    CP_WAIT(0);
    __syncthreads();

    uint32_t qf[4][4];
    #pragma unroll
    for (int kf = 0; kf < 4; kf++) {
        const uint32_t ro = (uint32_t)((wid * 16 + lrow) * ASTR) + (uint32_t)(kf * 32) + lcol;
        LDMX4(qf[kf][0], qf[kf][1], qf[kf][2], qf[kf][3], smb + ro);
    }

    float oacc[8][4];
    #pragma unroll
    for (int f = 0; f < 8; f++)
        #pragma unroll
        for (int r = 0; r < 4; r++) oacc[f][r] = 0.f;
    float m_i[2] = {-1e30f, -1e30f};
    float l_i[2] = {0.f, 0.f};

    const int nt = qb * 2 + 2;
    for (int kt = 0; kt < nt; kt++) {
        const int k0 = kt * BKV;
        if (kt + 1 < nt) {
            attn_load_kv(kvb + (uint32_t)(((kt + 1) & 1) * KVBUF), Kg, Vtg, bhoff, k0 + BKV, tid);
            CP_COMMIT();
        }

        if (q0w + 15 >= k0) {
            const uint32_t kb = kvb + (uint32_t)((kt & 1) * KVBUF);
            const uint32_t vb = kb + KVTILE;

            float s[8][4];
            #pragma unroll
            for (int f = 0; f < 8; f++)
                #pragma unroll
                for (int r = 0; r < 4; r++) s[f][r] = 0.f;

            #pragma unroll
            for (int kf = 0; kf < 4; kf++) {
                const uint32_t ko = (uint32_t)(kf * 32) + lcol;
                #pragma unroll
                for (int p = 0; p < 4; p++) {
                    uint32_t b0, b1, b2, b3;
                    LDMX4(b0, b1, b2, b3, kb + (uint32_t)((p * 16 + lrow) * ASTR) + ko);
                    MMA16816(s[2*p],   qf[kf][0], qf[kf][1], qf[kf][2], qf[kf][3], b0, b2);
                    MMA16816(s[2*p+1], qf[kf][0], qf[kf][1], qf[kf][2], qf[kf][3], b1, b3);
                }
            }

            if (k0 + 63 > q0w) {
                const int r0 = q0w + g, r1 = r0 + 8;
                #pragma unroll
                for (int ni = 0; ni < 8; ni++) {
                    const int c0 = k0 + ni * 8 + t * 2;
                    if (c0     > r0) s[ni][0] = -1e30f;
                    if (c0 + 1 > r0) s[ni][1] = -1e30f;
                    if (c0     > r1) s[ni][2] = -1e30f;
                    if (c0 + 1 > r1) s[ni][3] = -1e30f;
                }
            }

            float rmx0 = -1e30f, rmx1 = -1e30f;
            #pragma unroll
            for (int ni = 0; ni < 8; ni++) {
                rmx0 = fmaxf(rmx0, fmaxf(s[ni][0], s[ni][1]));
                rmx1 = fmaxf(rmx1, fmaxf(s[ni][2], s[ni][3]));
            }
            rmx0 = fmaxf(rmx0, __shfl_xor_sync(0xffffffffu, rmx0, 1));
            rmx0 = fmaxf(rmx0, __shfl_xor_sync(0xffffffffu, rmx0, 2));
            rmx1 = fmaxf(rmx1, __shfl_xor_sync(0xffffffffu, rmx1, 1));
            rmx1 = fmaxf(rmx1, __shfl_xor_sync(0xffffffffu, rmx1, 2));
            const float mn0 = fmaxf(m_i[0], rmx0);
            const float mn1 = fmaxf(m_i[1], rmx1);
            const float sc0 = __expf(m_i[0] - mn0);
            const float sc1 = __expf(m_i[1] - mn1);
            float rs0 = 0.f, rs1 = 0.f;
            #pragma unroll
            for (int ni = 0; ni < 8; ni++) {
                s[ni][0] = __expf(s[ni][0] - mn0); rs0 += s[ni][0];
                s[ni][1] = __expf(s[ni][1] - mn0); rs0 += s[ni][1];
                s[ni][2] = __expf(s[ni][2] - mn1); rs1 += s[ni][2];
                s[ni][3] = __expf(s[ni][3] - mn1); rs1 += s[ni][3];
            }
            rs0 += __shfl_xor_sync(0xffffffffu, rs0, 1);
            rs0 += __shfl_xor_sync(0xffffffffu, rs0, 2);
            rs1 += __shfl_xor_sync(0xffffffffu, rs1, 1);
            rs1 += __shfl_xor_sync(0xffffffffu, rs1, 2);
            m_i[0] = mn0; m_i[1] = mn1;
            l_i[0] = l_i[0] * sc0 + rs0;
            l_i[1] = l_i[1] * sc1 + rs1;
            #pragma unroll
            for (int f = 0; f < 8; f++) {
                oacc[f][0] *= sc0; oacc[f][1] *= sc0;
                oacc[f][2] *= sc1; oacc[f][3] *= sc1;
            }

            #pragma unroll
            for (int kf = 0; kf < 4; kf++) {
                const uint32_t pa0 = packh2(s[2*kf][0],   s[2*kf][1]);
                const uint32_t pa1 = packh2(s[2*kf][2],   s[2*kf][3]);
                const uint32_t pa2 = packh2(s[2*kf+1][0], s[2*kf+1][1]);
                const uint32_t pa3 = packh2(s[2*kf+1][2], s[2*kf+1][3]);
                const uint32_t ko = (uint32_t)(kf * 32) + lcol;
                #pragma unroll
                for (int p = 0; p < 4; p++) {
                    uint32_t b0, b1, b2, b3;
                    LDMX4(b0, b1, b2, b3, vb + (uint32_t)((p * 16 + lrow) * ASTR) + ko);
                    MMA16816(oacc[2*p],   pa0, pa1, pa2, pa3, b0, b2);
                    MMA16816(oacc[2*p+1], pa0, pa1, pa2, pa3, b1, b3);
                }
            }
        }
        CP_WAIT(0);
        __syncthreads();
    }

    const float inv0 = 1.0f / l_i[0];
    const float inv1 = 1.0f / l_i[1];
    const int b = bh >> 4, h = bh & 15;
    const int r0 = q0w + g, r1 = r0 + 8;
    #pragma unroll
    for (int ni = 0; ni < 8; ni++) {
        const int col = h * 64 + ni * 8 + t * 2;
        *(__half2*)(Og + (size_t)(b * SEQ + r0) * D_MODEL + col)
            = __floats2half2_rn(oacc[ni][0] * inv0, oacc[ni][1] * inv0);
        *(__half2*)(Og + (size_t)(b * SEQ + r1) * D_MODEL + col)
            = __floats2half2_rn(oacc[ni][2] * inv1, oacc[ni][3] * inv1);
    }
}

// ---------------------------------------------------------------------------
extern "C" void kernel_launch(void* const* d_in, const int* in_sizes, int n_in,
                              void* d_out, int out_size)
{
    const float* x   = (const float*)d_in[0];
    const float* w_q = (const float*)d_in[2];
    const float* b_q = (const float*)d_in[3];
    const float* w_k = (const float*)d_in[4];
    const float* b_k = (const float*)d_in[5];
    const float* w_v = (const float*)d_in[6];
    const float* b_v = (const float*)d_in[7];
    const float* w_o = (const float*)d_in[8];
    const float* b_o = (const float*)d_in[9];
    float* out = (float*)d_out;

    __half *x16, *w4, *qq, *kk, *vt, *oo;
    cudaGetSymbolAddress((void**)&x16, g_x16);
    cudaGetSymbolAddress((void**)&w4, g_w4);
    cudaGetSymbolAddress((void**)&qq, g_q);
    cudaGetSymbolAddress((void**)&kk, g_k);
    cudaGetSymbolAddress((void**)&vt, g_vt);
    cudaGetSymbolAddress((void**)&oo, g_o);

    const size_t WSZ = (size_t)D_MODEL * D_MODEL;
    __half *wq = w4, *wk = w4 + WSZ, *wv = w4 + 2 * WSZ, *wo = w4 + 3 * WSZ;

    cudaFuncSetAttribute(gemm_hmma, cudaFuncAttributeMaxDynamicSharedMemorySize, GEMM_SMEM);
    cudaFuncSetAttribute(attn_hmma, cudaFuncAttributeMaxDynamicSharedMemorySize, ATTN_SMEM);

    const int n4 = M_ROWS * D_MODEL / 4;
    cvtx<<<(n4 + 255) / 256, 256>>>(x, x16, n4);
    wT16<<<dim3(D_MODEL / 32, D_MODEL / 32, 4), dim3(32, 8)>>>(w_q, w_k, w_v, w_o, w4);

    dim3 gg(D_MODEL / 128, M_ROWS / 128);
    gemm_hmma<<<gg, 256, GEMM_SMEM>>>(x16, wq, b_q, 1, qq);
    gemm_hmma<<<gg, 256, GEMM_SMEM>>>(x16, wk, b_k, 2, kk);
    gemm_hmma<<<gg, 256, GEMM_SMEM>>>(x16, wv, b_v, 3, vt);

    attn_hmma<<<dim3(SEQ / BQ, 64), 256, ATTN_SMEM>>>(qq, kk, vt, oo);

    gemm_hmma<<<gg, 256, GEMM_SMEM>>>(oo, wo, b_o, 0, out);
}

// round 8
// speedup vs baseline: 7.5861x; 1.0365x over previous
#include <cuda_runtime.h>
#include <cuda_fp16.h>
#include <cstdint>
#include <cstddef>

#define D_MODEL 1024
#define N_HEADS 16
#define BATCH   4
#define SEQ     2048
#define DK      64
#define M_ROWS  (BATCH * SEQ)
#define BHT     (64 * SEQ * DK)

__device__ __half g_x16[M_ROWS * D_MODEL];
__device__ __half g_w4[4 * D_MODEL * D_MODEL];
__device__ __half g_q [BHT];            // [bh][t][dk], pre-scaled by 0.125
__device__ __half g_k [BHT];            // [bh][t][dk]
__device__ __half g_vt[BHT];            // [bh][dk][t]
__device__ __half g_o [M_ROWS * D_MODEL];

__device__ __forceinline__ uint32_t smem_u32(const void* p) {
    uint32_t a;
    asm("{ .reg .u64 t; cvta.to.shared.u64 t, %1; cvt.u32.u64 %0, t; }" : "=r"(a) : "l"(p));
    return a;
}
#define CP_ASYNC16(dst, src) \
    asm volatile("cp.async.cg.shared.global [%0], [%1], 16;" :: "r"(dst), "l"(src))
#define CP_COMMIT()  asm volatile("cp.async.commit_group;" ::: "memory")
#define CP_WAIT(n)   asm volatile("cp.async.wait_group %0;" :: "n"(n) : "memory")
#define LDMX4(r0, r1, r2, r3, addr) \
    asm volatile("ldmatrix.sync.aligned.m8n8.x4.shared.b16 {%0,%1,%2,%3}, [%4];" \
        : "=r"(r0), "=r"(r1), "=r"(r2), "=r"(r3) : "r"(addr))
#define MMA16816(acc, a0, a1, a2, a3, b0, b1) \
    asm volatile("mma.sync.aligned.m16n8k16.row.col.f32.f16.f16.f32 " \
        "{%0,%1,%2,%3},{%4,%5,%6,%7},{%8,%9},{%0,%1,%2,%3};" \
        : "+f"((acc)[0]), "+f"((acc)[1]), "+f"((acc)[2]), "+f"((acc)[3]) \
        : "r"(a0), "r"(a1), "r"(a2), "r"(a3), "r"(b0), "r"(b1))

__device__ __forceinline__ uint32_t packh2(float x, float y) {
    __half2 h = __floats2half2_rn(x, y);
    return *(uint32_t*)&h;
}

// ---------------- conversions ----------------
__global__ __launch_bounds__(256) void cvtx(const float* __restrict__ in,
                                            __half* __restrict__ out, int n4)
{
    int i = blockIdx.x * 256 + threadIdx.x;
    if (i >= n4) return;
    float4 v = ((const float4*)in)[i];
    *(__half2*)(out + 4 * (size_t)i)     = __floats2half2_rn(v.x, v.y);
    *(__half2*)(out + 4 * (size_t)i + 2) = __floats2half2_rn(v.z, v.w);
}

__global__ void wT16(const float* w0, const float* w1, const float* w2,
                     const float* w3, __half* __restrict__ dst)
{
    const float* W = (blockIdx.z == 0) ? w0 : (blockIdx.z == 1) ? w1
                   : (blockIdx.z == 2) ? w2 : w3;
    __half* Wt = dst + (size_t)blockIdx.z * D_MODEL * D_MODEL;
    __shared__ float t[32][33];
    int tx = threadIdx.x, ty = threadIdx.y;
    int n0 = blockIdx.x * 32, k0 = blockIdx.y * 32;
    #pragma unroll
    for (int j = 0; j < 32; j += 8)
        t[ty + j][tx] = W[(size_t)(k0 + ty + j) * D_MODEL + n0 + tx];
    __syncthreads();
    #pragma unroll
    for (int j = 0; j < 32; j += 8)
        Wt[(size_t)(n0 + ty + j) * D_MODEL + k0 + tx] = __float2half_rn(t[tx][ty + j]);
}

// ---------------- GEMM core (A[M,K] @ B[N,K]^T, 128x128 tile) ----------------
#define TKk 64
#define NKT (D_MODEL / TKk)          // 16
#define RSTR 144
#define TILEB (128 * RSTR)
#define STAGEB (2 * TILEB)
#define NSTAGE 3
#define GEMM_SMEM (NSTAGE * STAGEB)  // 110592

__device__ __forceinline__ void load_stage(
    uint32_t base, const __half* __restrict__ A, const __half* __restrict__ B,
    int m0, int n0, int k0, int tid)
{
    #pragma unroll
    for (int it = 0; it < 4; it++) {
        const int idx = tid + it * 256;
        const int r = idx >> 3;
        const int c = idx & 7;
        const uint32_t so = (uint32_t)(r * RSTR + c * 16);
        CP_ASYNC16(base + so,         A + (size_t)(m0 + r) * D_MODEL + k0 + c * 8);
        CP_ASYNC16(base + TILEB + so, B + (size_t)(n0 + r) * D_MODEL + k0 + c * 8);
    }
}

__device__ __forceinline__ void gemm_core(
    uint32_t smb, const __half* A, const __half* Bw,
    int m0, int n0, int tid, float acc[4][4][4])
{
    const int wid = tid >> 5;
    const int lane = tid & 31;
    const int warp_m = wid & 1;
    const int warp_n = wid >> 1;
    const int lrow = lane & 15;
    const uint32_t lcol = (uint32_t)((lane >> 4) * 16);

    load_stage(smb,          A, Bw, m0, n0, 0,   tid); CP_COMMIT();
    load_stage(smb + STAGEB, A, Bw, m0, n0, TKk, tid); CP_COMMIT();

    int stage = 0;
    for (int kt = 0; kt < NKT; kt++) {
        CP_WAIT(1);
        __syncthreads();
        if (kt + 2 < NKT) {
            int ns = stage + 2; if (ns >= NSTAGE) ns -= NSTAGE;
            load_stage(smb + (uint32_t)(ns * STAGEB), A, Bw, m0, n0, (kt + 2) * TKk, tid);
        }
        CP_COMMIT();

        const uint32_t st = smb + (uint32_t)(stage * STAGEB);
        #pragma unroll
        for (int ks = 0; ks < 4; ks++) {
            const uint32_t ko = (uint32_t)(ks * 32) + lcol;
            uint32_t b[2][4], a[4][4];
            #pragma unroll
            for (int p = 0; p < 2; p++)
                LDMX4(b[p][0], b[p][1], b[p][2], b[p][3],
                      st + TILEB + (uint32_t)((warp_n * 32 + p * 16 + lrow) * RSTR) + ko);
            #pragma unroll
            for (int mi = 0; mi < 4; mi++)
                LDMX4(a[mi][0], a[mi][1], a[mi][2], a[mi][3],
                      st + (uint32_t)((warp_m * 64 + mi * 16 + lrow) * RSTR) + ko);
            #pragma unroll
            for (int mi = 0; mi < 4; mi++)
                #pragma unroll
                for (int ni = 0; ni < 4; ni++)
                    MMA16816(acc[mi][ni], a[mi][0], a[mi][1], a[mi][2], a[mi][3],
                             b[ni >> 1][ni & 1], b[ni >> 1][2 + (ni & 1)]);
        }
        if (++stage >= NSTAGE) stage = 0;
    }
}

// Fused QKV projection: blockIdx.z = 0(Q) / 1(K) / 2(Vt)
__global__ __launch_bounds__(256) void gemm_qkv(
    const __half* __restrict__ x16, const __half* __restrict__ w4,
    const float* __restrict__ b_q, const float* __restrict__ b_k,
    const float* __restrict__ b_v,
    __half* __restrict__ qq, __half* __restrict__ kk, __half* __restrict__ vt)
{
    extern __shared__ char sm[];
    const uint32_t smb = smem_u32(sm);
    const int tid = threadIdx.x;
    const int z = blockIdx.z;
    const int m0 = blockIdx.y * 128;
    const int n0 = blockIdx.x * 128;
    const __half* Bw = w4 + (size_t)z * D_MODEL * D_MODEL;
    const float* bias = (z == 0) ? b_q : (z == 1) ? b_k : b_v;

    float acc[4][4][4];
    #pragma unroll
    for (int i = 0; i < 4; i++)
        #pragma unroll
        for (int j = 0; j < 4; j++)
            #pragma unroll
            for (int r = 0; r < 4; r++) acc[i][j][r] = 0.f;

    gemm_core(smb, x16, Bw, m0, n0, tid, acc);

    const int wid = tid >> 5;
    const int lane = tid & 31;
    const int g = lane >> 2;
    const int t = lane & 3;
    #pragma unroll
    for (int mi = 0; mi < 4; mi++) {
        #pragma unroll
        for (int ni = 0; ni < 4; ni++) {
            const int n = n0 + (wid >> 1) * 32 + ni * 8 + t * 2;
            const float b0 = bias[n], b1 = bias[n + 1];
            #pragma unroll
            for (int hf = 0; hf < 2; hf++) {
                const int m = m0 + (wid & 1) * 64 + mi * 16 + g + hf * 8;
                const float v0 = acc[mi][ni][hf * 2 + 0] + b0;
                const float v1 = acc[mi][ni][hf * 2 + 1] + b1;
                const int bb = m >> 11, tt = m & (SEQ - 1);
                const int hh = n >> 6, dd = n & (DK - 1);
                if (z == 0) {
                    *(__half2*)(qq + ((size_t)(bb * 16 + hh) * SEQ + tt) * DK + dd)
                        = __floats2half2_rn(v0 * 0.125f, v1 * 0.125f);
                } else if (z == 1) {
                    *(__half2*)(kk + ((size_t)(bb * 16 + hh) * SEQ + tt) * DK + dd)
                        = __floats2half2_rn(v0, v1);
                } else {
                    const size_t idx = ((size_t)(bb * 16 + hh) * DK + dd) * SEQ + tt;
                    vt[idx]       = __float2half_rn(v0);
                    vt[idx + SEQ] = __float2half_rn(v1);
                }
            }
        }
    }
}

// Output projection (fp32 out)
__global__ __launch_bounds__(256) void gemm_oproj(
    const __half* __restrict__ A, const __half* __restrict__ Bw,
    const float* __restrict__ bias, float* __restrict__ out)
{
    extern __shared__ char sm[];
    const uint32_t smb = smem_u32(sm);
    const int tid = threadIdx.x;
    const int m0 = blockIdx.y * 128;
    const int n0 = blockIdx.x * 128;

    float acc[4][4][4];
    #pragma unroll
    for (int i = 0; i < 4; i++)
        #pragma unroll
        for (int j = 0; j < 4; j++)
            #pragma unroll
            for (int r = 0; r < 4; r++) acc[i][j][r] = 0.f;

    gemm_core(smb, A, Bw, m0, n0, tid, acc);

    const int wid = tid >> 5;
    const int lane = tid & 31;
    const int g = lane >> 2;
    const int t = lane & 3;
    #pragma unroll
    for (int mi = 0; mi < 4; mi++) {
        #pragma unroll
        for (int ni = 0; ni < 4; ni++) {
            const int n = n0 + (wid >> 1) * 32 + ni * 8 + t * 2;
            const float b0 = bias[n], b1 = bias[n + 1];
            #pragma unroll
            for (int hf = 0; hf < 2; hf++) {
                const int m = m0 + (wid & 1) * 64 + mi * 16 + g + hf * 8;
                *(float2*)(out + (size_t)m * D_MODEL + n)
                    = make_float2(acc[mi][ni][hf * 2 + 0] + b0,
                                  acc[mi][ni][hf * 2 + 1] + b1);
            }
        }
    }
}

// ---------------- FlashAttention-2 on HMMA, 3-stage KV ring ----------------
#define BQ 128
#define BKV 64
#define ASTR 144
#define QTILE (BQ * ASTR)
#define KVTILE (BKV * ASTR)
#define KVBUF (2 * KVTILE)
#define ATTN_SMEM (QTILE + 3 * KVBUF)   // 73728

__device__ __forceinline__ void attn_load_kv(
    uint32_t base, const __half* __restrict__ Kg, const __half* __restrict__ Vtg,
    size_t bhoff, int k0, int tid)
{
    #pragma unroll
    for (int it = 0; it < 2; it++) {
        const int i = tid + it * 256;
        const int r = i >> 3;
        const int c = i & 7;
        const uint32_t so = (uint32_t)(r * ASTR + c * 16);
        CP_ASYNC16(base + so,          Kg  + bhoff + (size_t)(k0 + r) * DK + c * 8);
        CP_ASYNC16(base + KVTILE + so, Vtg + bhoff + (size_t)r * SEQ + k0 + c * 8);
    }
}

__global__ __launch_bounds__(256) void attn_hmma(
    const __half* __restrict__ Qg, const __half* __restrict__ Kg,
    const __half* __restrict__ Vtg, __half* __restrict__ Og)
{
    extern __shared__ char sm[];
    const uint32_t smb = smem_u32(sm);
    const int tid = threadIdx.x;
    const int wid = tid >> 5;
    const int lane = tid & 31;
    const int qb = gridDim.x - 1 - blockIdx.x;
    const int bh = blockIdx.y;
    const int q0 = qb * BQ;
    const size_t bhoff = (size_t)bh * SEQ * DK;
    const int lrow = lane & 15;
    const uint32_t lcol = (uint32_t)((lane >> 4) * 16);
    const int g = lane >> 2;
    const int t = lane & 3;
    const int q0w = q0 + wid * 16;
    const uint32_t kvb = smb + QTILE;
    const int nt = qb * 2 + 2;

    // group 0: Q tile + KV tile 0 ; group 1: KV tile 1
    #pragma unroll
    for (int it = 0; it < 4; it++) {
        const int i = tid + it * 256;
        const int r = i >> 3;
        const int c = i & 7;
        CP_ASYNC16(smb + (uint32_t)(r * ASTR + c * 16),
                   Qg + bhoff + (size_t)(q0 + r) * DK + c * 8);
    }
    attn_load_kv(kvb, Kg, Vtg, bhoff, 0, tid);
    CP_COMMIT();
    attn_load_kv(kvb + KVBUF, Kg, Vtg, bhoff, BKV, tid);
    CP_COMMIT();

    uint32_t qf[4][4];
    float oacc[8][4];
    #pragma unroll
    for (int f = 0; f < 8; f++)
        #pragma unroll
        for (int r = 0; r < 4; r++) oacc[f][r] = 0.f;
    float m_i[2] = {-1e30f, -1e30f};
    float l_i[2] = {0.f, 0.f};

    int stage = 0;
    for (int kt = 0; kt < nt; kt++) {
        const int k0 = kt * BKV;
        CP_WAIT(1);
        __syncthreads();
        if (kt + 2 < nt) {
            int ns = stage + 2; if (ns >= 3) ns -= 3;
            attn_load_kv(kvb + (uint32_t)(ns * KVBUF), Kg, Vtg, bhoff, k0 + 2 * BKV, tid);
        }
        CP_COMMIT();

        if (kt == 0) {
            #pragma unroll
            for (int kf = 0; kf < 4; kf++) {
                const uint32_t ro = (uint32_t)((wid * 16 + lrow) * ASTR) + (uint32_t)(kf * 32) + lcol;
                LDMX4(qf[kf][0], qf[kf][1], qf[kf][2], qf[kf][3], smb + ro);
            }
        }

        if (q0w + 15 >= k0) {
            const uint32_t kb = kvb + (uint32_t)(stage * KVBUF);
            const uint32_t vb = kb + KVTILE;

            float s[8][4];
            #pragma unroll
            for (int f = 0; f < 8; f++)
                #pragma unroll
                for (int r = 0; r < 4; r++) s[f][r] = 0.f;

            #pragma unroll
            for (int kf = 0; kf < 4; kf++) {
                const uint32_t ko = (uint32_t)(kf * 32) + lcol;
                #pragma unroll
                for (int p = 0; p < 4; p++) {
                    uint32_t b0, b1, b2, b3;
                    LDMX4(b0, b1, b2, b3, kb + (uint32_t)((p * 16 + lrow) * ASTR) + ko);
                    MMA16816(s[2*p],   qf[kf][0], qf[kf][1], qf[kf][2], qf[kf][3], b0, b2);
                    MMA16816(s[2*p+1], qf[kf][0], qf[kf][1], qf[kf][2], qf[kf][3], b1, b3);
                }
            }

            if (k0 + 63 > q0w) {
                const int r0 = q0w + g, r1 = r0 + 8;
                #pragma unroll
                for (int ni = 0; ni < 8; ni++) {
                    const int c0 = k0 + ni * 8 + t * 2;
                    if (c0     > r0) s[ni][0] = -1e30f;
                    if (c0 + 1 > r0) s[ni][1] = -1e30f;
                    if (c0     > r1) s[ni][2] = -1e30f;
                    if (c0 + 1 > r1) s[ni][3] = -1e30f;
                }
            }

            float rmx0 = -1e30f, rmx1 = -1e30f;
            #pragma unroll
            for (int ni = 0; ni < 8; ni++) {
                rmx0 = fmaxf(rmx0, fmaxf(s[ni][0], s[ni][1]));
                rmx1 = fmaxf(rmx1, fmaxf(s[ni][2], s[ni][3]));
            }
            rmx0 = fmaxf(rmx0, __shfl_xor_sync(0xffffffffu, rmx0, 1));
            rmx0 = fmaxf(rmx0, __shfl_xor_sync(0xffffffffu, rmx0, 2));
            rmx1 = fmaxf(rmx1, __shfl_xor_sync(0xffffffffu, rmx1, 1));
            rmx1 = fmaxf(rmx1, __shfl_xor_sync(0xffffffffu, rmx1, 2));
            const float mn0 = fmaxf(m_i[0], rmx0);
            const float mn1 = fmaxf(m_i[1], rmx1);
            const float sc0 = __expf(m_i[0] - mn0);
            const float sc1 = __expf(m_i[1] - mn1);
            float rs0 = 0.f, rs1 = 0.f;
            #pragma unroll
            for (int ni = 0; ni < 8; ni++) {
                s[ni][0] = __expf(s[ni][0] - mn0); rs0 += s[ni][0];
                s[ni][1] = __expf(s[ni][1] - mn0); rs0 += s[ni][1];
                s[ni][2] = __expf(s[ni][2] - mn1); rs1 += s[ni][2];
                s[ni][3] = __expf(s[ni][3] - mn1); rs1 += s[ni][3];
            }
            rs0 += __shfl_xor_sync(0xffffffffu, rs0, 1);
            rs0 += __shfl_xor_sync(0xffffffffu, rs0, 2);
            rs1 += __shfl_xor_sync(0xffffffffu, rs1, 1);
            rs1 += __shfl_xor_sync(0xffffffffu, rs1, 2);
            m_i[0] = mn0; m_i[1] = mn1;
            l_i[0] = l_i[0] * sc0 + rs0;
            l_i[1] = l_i[1] * sc1 + rs1;
            #pragma unroll
            for (int f = 0; f < 8; f++) {
                oacc[f][0] *= sc0; oacc[f][1] *= sc0;
                oacc[f][2] *= sc1; oacc[f][3] *= sc1;
            }

            #pragma unroll
            for (int kf = 0; kf < 4; kf++) {
                const uint32_t pa0 = packh2(s[2*kf][0],   s[2*kf][1]);
                const uint32_t pa1 = packh2(s[2*kf][2],   s[2*kf][3]);
                const uint32_t pa2 = packh2(s[2*kf+1][0], s[2*kf+1][1]);
                const uint32_t pa3 = packh2(s[2*kf+1][2], s[2*kf+1][3]);
                const uint32_t ko = (uint32_t)(kf * 32) + lcol;
                #pragma unroll
                for (int p = 0; p < 4; p++) {
                    uint32_t b0, b1, b2, b3;
                    LDMX4(b0, b1, b2, b3, vb + (uint32_t)((p * 16 + lrow) * ASTR) + ko);
                    MMA16816(oacc[2*p],   pa0, pa1, pa2, pa3, b0, b2);
                    MMA16816(oacc[2*p+1], pa0, pa1, pa2, pa3, b1, b3);
                }
            }
        }
        if (++stage >= 3) stage = 0;
    }

    const float inv0 = 1.0f / l_i[0];
    const float inv1 = 1.0f / l_i[1];
    const int b = bh >> 4, h = bh & 15;
    const int r0 = q0w + g, r1 = r0 + 8;
    #pragma unroll
    for (int ni = 0; ni < 8; ni++) {
        const int col = h * 64 + ni * 8 + t * 2;
        *(__half2*)(Og + (size_t)(b * SEQ + r0) * D_MODEL + col)
            = __floats2half2_rn(oacc[ni][0] * inv0, oacc[ni][1] * inv0);
        *(__half2*)(Og + (size_t)(b * SEQ + r1) * D_MODEL + col)
            = __floats2half2_rn(oacc[ni][2] * inv1, oacc[ni][3] * inv1);
    }
}

// ---------------------------------------------------------------------------
extern "C" void kernel_launch(void* const* d_in, const int* in_sizes, int n_in,
                              void* d_out, int out_size)
{
    const float* x   = (const float*)d_in[0];
    const float* w_q = (const float*)d_in[2];
    const float* b_q = (const float*)d_in[3];
    const float* w_k = (const float*)d_in[4];
    const float* b_k = (const float*)d_in[5];
    const float* w_v = (const float*)d_in[6];
    const float* b_v = (const float*)d_in[7];
    const float* w_o = (const float*)d_in[8];
    const float* b_o = (const float*)d_in[9];
    float* out = (float*)d_out;

    __half *x16, *w4, *qq, *kk, *vt, *oo;
    cudaGetSymbolAddress((void**)&x16, g_x16);
    cudaGetSymbolAddress((void**)&w4, g_w4);
    cudaGetSymbolAddress((void**)&qq, g_q);
    cudaGetSymbolAddress((void**)&kk, g_k);
    cudaGetSymbolAddress((void**)&vt, g_vt);
    cudaGetSymbolAddress((void**)&oo, g_o);

    const size_t WSZ = (size_t)D_MODEL * D_MODEL;
    __half *wo = w4 + 3 * WSZ;

    cudaFuncSetAttribute(gemm_qkv,   cudaFuncAttributeMaxDynamicSharedMemorySize, GEMM_SMEM);
    cudaFuncSetAttribute(gemm_oproj, cudaFuncAttributeMaxDynamicSharedMemorySize, GEMM_SMEM);
    cudaFuncSetAttribute(attn_hmma,  cudaFuncAttributeMaxDynamicSharedMemorySize, ATTN_SMEM);

    const int n4 = M_ROWS * D_MODEL / 4;
    cvtx<<<(n4 + 255) / 256, 256>>>(x, x16, n4);
    wT16<<<dim3(D_MODEL / 32, D_MODEL / 32, 4), dim3(32, 8)>>>(w_q, w_k, w_v, w_o, w4);

    gemm_qkv<<<dim3(D_MODEL / 128, M_ROWS / 128, 3), 256, GEMM_SMEM>>>(
        x16, w4, b_q, b_k, b_v, qq, kk, vt);

    attn_hmma<<<dim3(SEQ / BQ, 64), 256, ATTN_SMEM>>>(qq, kk, vt, oo);

    gemm_oproj<<<dim3(D_MODEL / 128, M_ROWS / 128), 256, GEMM_SMEM>>>(oo, wo, b_o, out);
}

// round 10
// speedup vs baseline: 7.9667x; 1.0502x over previous
#include <cuda_runtime.h>
#include <cuda_fp16.h>
#include <cstdint>
#include <cstddef>

#define D_MODEL 1024
#define N_HEADS 16
#define BATCH   4
#define SEQ     2048
#define DK      64
#define M_ROWS  (BATCH * SEQ)
#define BHT     (64 * SEQ * DK)

// Q pre-scale: (1/sqrt(dk)) * log2(e) so softmax uses raw ex2
#define QSCALE 0.18033688011112042f

__device__ __half g_x16[M_ROWS * D_MODEL];
__device__ __half g_w4[4 * D_MODEL * D_MODEL];
__device__ __half g_q [BHT];            // [bh][t][dk], pre-scaled by QSCALE
__device__ __half g_k [BHT];            // [bh][t][dk]
__device__ __half g_vt[BHT];            // [bh][dk][t]
__device__ __half g_o [M_ROWS * D_MODEL];

__device__ __forceinline__ uint32_t smem_u32(const void* p) {
    uint32_t a;
    asm("{ .reg .u64 t; cvta.to.shared.u64 t, %1; cvt.u32.u64 %0, t; }" : "=r"(a) : "l"(p));
    return a;
}
#define CP_ASYNC16(dst, src) \
    asm volatile("cp.async.cg.shared.global [%0], [%1], 16;" :: "r"(dst), "l"(src))
#define CP_COMMIT()  asm volatile("cp.async.commit_group;" ::: "memory")
#define CP_WAIT(n)   asm volatile("cp.async.wait_group %0;" :: "n"(n) : "memory")
#define LDMX4(r0, r1, r2, r3, addr) \
    asm volatile("ldmatrix.sync.aligned.m8n8.x4.shared.b16 {%0,%1,%2,%3}, [%4];" \
        : "=r"(r0), "=r"(r1), "=r"(r2), "=r"(r3) : "r"(addr))
#define MMA16816(acc, a0, a1, a2, a3, b0, b1) \
    asm volatile("mma.sync.aligned.m16n8k16.row.col.f32.f16.f16.f32 " \
        "{%0,%1,%2,%3},{%4,%5,%6,%7},{%8,%9},{%0,%1,%2,%3};" \
        : "+f"((acc)[0]), "+f"((acc)[1]), "+f"((acc)[2]), "+f"((acc)[3]) \
        : "r"(a0), "r"(a1), "r"(a2), "r"(a3), "r"(b0), "r"(b1))

__device__ __forceinline__ float ex2(float x) {
    float r;
    asm("ex2.approx.ftz.f32 %0, %1;" : "=f"(r) : "f"(x));
    return r;
}
__device__ __forceinline__ uint32_t packh2(float x, float y) {
    __half2 h = __floats2half2_rn(x, y);
    return *(uint32_t*)&h;
}

// ---------------- fused prep: x fp32->fp16 (blocks 0..8191) + 4x weight transpose ----------------
__global__ __launch_bounds__(256) void prep(
    const float* __restrict__ x, const float* __restrict__ w0,
    const float* __restrict__ w1, const float* __restrict__ w2,
    const float* __restrict__ w3, __half* __restrict__ x16,
    __half* __restrict__ w4)
{
    __shared__ float t[32][33];
    const int bx = blockIdx.x;
    const int tid = threadIdx.x;
    if (bx < 8192) {
        const int i = bx * 256 + tid;   // n4 = 2M, exactly 8192*256
        float4 v = ((const float4*)x)[i];
        *(__half2*)(x16 + 4 * (size_t)i)     = __floats2half2_rn(v.x, v.y);
        *(__half2*)(x16 + 4 * (size_t)i + 2) = __floats2half2_rn(v.z, v.w);
    } else {
        const int b2 = bx - 8192;               // 0..4095
        const int z  = b2 >> 10;                // weight index
        const float* W = (z == 0) ? w0 : (z == 1) ? w1 : (z == 2) ? w2 : w3;
        __half* Wt = w4 + (size_t)z * D_MODEL * D_MODEL;
        const int n0 = (b2 & 31) * 32;
        const int k0 = ((b2 >> 5) & 31) * 32;
        const int tx = tid & 31, ty = tid >> 5; // ty 0..7
        #pragma unroll
        for (int j = 0; j < 32; j += 8)
            t[ty + j][tx] = W[(size_t)(k0 + ty + j) * D_MODEL + n0 + tx];
        __syncthreads();
        #pragma unroll
        for (int j = 0; j < 32; j += 8)
            Wt[(size_t)(n0 + ty + j) * D_MODEL + k0 + tx] = __float2half_rn(t[tx][ty + j]);
    }
}

// ---------------- GEMM core (A[M,K] @ B[N,K]^T, 128x128 tile) ----------------
#define TKk 64
#define NKT (D_MODEL / TKk)
#define RSTR 144
#define TILEB (128 * RSTR)
#define STAGEB (2 * TILEB)
#define NSTAGE 3
#define GEMM_SMEM (NSTAGE * STAGEB)  // 110592

__device__ __forceinline__ void load_stage(
    uint32_t base, const __half* __restrict__ A, const __half* __restrict__ B,
    int m0, int n0, int k0, int tid)
{
    #pragma unroll
    for (int it = 0; it < 4; it++) {
        const int idx = tid + it * 256;
        const int r = idx >> 3;
        const int c = idx & 7;
        const uint32_t so = (uint32_t)(r * RSTR + c * 16);
        CP_ASYNC16(base + so,         A + (size_t)(m0 + r) * D_MODEL + k0 + c * 8);
        CP_ASYNC16(base + TILEB + so, B + (size_t)(n0 + r) * D_MODEL + k0 + c * 8);
    }
}

__device__ __forceinline__ void gemm_core(
    uint32_t smb, const __half* A, const __half* Bw,
    int m0, int n0, int tid, float acc[4][4][4])
{
    const int wid = tid >> 5;
    const int lane = tid & 31;
    const int warp_m = wid & 1;
    const int warp_n = wid >> 1;
    const int lrow = lane & 15;
    const uint32_t lcol = (uint32_t)((lane >> 4) * 16);

    load_stage(smb,          A, Bw, m0, n0, 0,   tid); CP_COMMIT();
    load_stage(smb + STAGEB, A, Bw, m0, n0, TKk, tid); CP_COMMIT();

    int stage = 0;
    for (int kt = 0; kt < NKT; kt++) {
        CP_WAIT(1);
        __syncthreads();
        if (kt + 2 < NKT) {
            int ns = stage + 2; if (ns >= NSTAGE) ns -= NSTAGE;
            load_stage(smb + (uint32_t)(ns * STAGEB), A, Bw, m0, n0, (kt + 2) * TKk, tid);
        }
        CP_COMMIT();

        const uint32_t st = smb + (uint32_t)(stage * STAGEB);
        #pragma unroll
        for (int ks = 0; ks < 4; ks++) {
            const uint32_t ko = (uint32_t)(ks * 32) + lcol;
            uint32_t b[2][4], a[4][4];
            #pragma unroll
            for (int p = 0; p < 2; p++)
                LDMX4(b[p][0], b[p][1], b[p][2], b[p][3],
                      st + TILEB + (uint32_t)((warp_n * 32 + p * 16 + lrow) * RSTR) + ko);
            #pragma unroll
            for (int mi = 0; mi < 4; mi++)
                LDMX4(a[mi][0], a[mi][1], a[mi][2], a[mi][3],
                      st + (uint32_t)((warp_m * 64 + mi * 16 + lrow) * RSTR) + ko);
            #pragma unroll
            for (int mi = 0; mi < 4; mi++)
                #pragma unroll
                for (int ni = 0; ni < 4; ni++)
                    MMA16816(acc[mi][ni], a[mi][0], a[mi][1], a[mi][2], a[mi][3],
                             b[ni >> 1][ni & 1], b[ni >> 1][2 + (ni & 1)]);
        }
        if (++stage >= NSTAGE) stage = 0;
    }
}

// Fused QKV projection: blockIdx.z = 0(Q) / 1(K) / 2(Vt)
__global__ __launch_bounds__(256) void gemm_qkv(
    const __half* __restrict__ x16, const __half* __restrict__ w4,
    const float* __restrict__ b_q, const float* __restrict__ b_k,
    const float* __restrict__ b_v,
    __half* __restrict__ qq, __half* __restrict__ kk, __half* __restrict__ vt)
{
    extern __shared__ char sm[];
    const uint32_t smb = smem_u32(sm);
    const int tid = threadIdx.x;
    const int z = blockIdx.z;
    const int m0 = blockIdx.y * 128;
    const int n0 = blockIdx.x * 128;
    const __half* Bw = w4 + (size_t)z * D_MODEL * D_MODEL;
    const float* bias = (z == 0) ? b_q : (z == 1) ? b_k : b_v;

    float acc[4][4][4];
    #pragma unroll
    for (int i = 0; i < 4; i++)
        #pragma unroll
        for (int j = 0; j < 4; j++)
            #pragma unroll
            for (int r = 0; r < 4; r++) acc[i][j][r] = 0.f;

    gemm_core(smb, x16, Bw, m0, n0, tid, acc);

    const int wid = tid >> 5;
    const int lane = tid & 31;
    const int g = lane >> 2;
    const int t = lane & 3;
    #pragma unroll
    for (int mi = 0; mi < 4; mi++) {
        #pragma unroll
        for (int ni = 0; ni < 4; ni++) {
            const int n = n0 + (wid >> 1) * 32 + ni * 8 + t * 2;
            const float b0 = bias[n], b1 = bias[n + 1];
            #pragma unroll
            for (int hf = 0; hf < 2; hf++) {
                const int m = m0 + (wid & 1) * 64 + mi * 16 + g + hf * 8;
                const float v0 = acc[mi][ni][hf * 2 + 0] + b0;
                const float v1 = acc[mi][ni][hf * 2 + 1] + b1;
                const int bb = m >> 11, tt = m & (SEQ - 1);
                const int hh = n >> 6, dd = n & (DK - 1);
                if (z == 0) {
                    *(__half2*)(qq + ((size_t)(bb * 16 + hh) * SEQ + tt) * DK + dd)
                        = __floats2half2_rn(v0 * QSCALE, v1 * QSCALE);
                } else if (z == 1) {
                    *(__half2*)(kk + ((size_t)(bb * 16 + hh) * SEQ + tt) * DK + dd)
                        = __floats2half2_rn(v0, v1);
                } else {
                    const size_t idx = ((size_t)(bb * 16 + hh) * DK + dd) * SEQ + tt;
                    vt[idx]       = __float2half_rn(v0);
                    vt[idx + SEQ] = __float2half_rn(v1);
                }
            }
        }
    }
}

// Output projection (fp32 out)
__global__ __launch_bounds__(256) void gemm_oproj(
    const __half* __restrict__ A, const __half* __restrict__ Bw,
    const float* __restrict__ bias, float* __restrict__ out)
{
    extern __shared__ char sm[];
    const uint32_t smb = smem_u32(sm);
    const int tid = threadIdx.x;
    const int m0 = blockIdx.y * 128;
    const int n0 = blockIdx.x * 128;

    float acc[4][4][4];
    #pragma unroll
    for (int i = 0; i < 4; i++)
        #pragma unroll
        for (int j = 0; j < 4; j++)
            #pragma unroll
            for (int r = 0; r < 4; r++) acc[i][j][r] = 0.f;

    gemm_core(smb, A, Bw, m0, n0, tid, acc);

    const int wid = tid >> 5;
    const int lane = tid & 31;
    const int g = lane >> 2;
    const int t = lane & 3;
    #pragma unroll
    for (int mi = 0; mi < 4; mi++) {
        #pragma unroll
        for (int ni = 0; ni < 4; ni++) {
            const int n = n0 + (wid >> 1) * 32 + ni * 8 + t * 2;
            const float b0 = bias[n], b1 = bias[n + 1];
            #pragma unroll
            for (int hf = 0; hf < 2; hf++) {
                const int m = m0 + (wid & 1) * 64 + mi * 16 + g + hf * 8;
                *(float2*)(out + (size_t)m * D_MODEL + n)
                    = make_float2(acc[mi][ni][hf * 2 + 0] + b0,
                                  acc[mi][ni][hf * 2 + 1] + b1);
            }
        }
    }
}

// ---------------- FlashAttention-2 on HMMA, 3-stage KV ring, base-2 softmax ----------------
#define BQ 128
#define BKV 64
#define ASTR 144
#define QTILE (BQ * ASTR)
#define KVTILE (BKV * ASTR)
#define KVBUF (2 * KVTILE)
#define ATTN_SMEM (QTILE + 3 * KVBUF)   // 73728

__device__ __forceinline__ void attn_load_kv(
    uint32_t base, const __half* __restrict__ Kg, const __half* __restrict__ Vtg,
    size_t bhoff, int k0, int tid)
{
    #pragma unroll
    for (int it = 0; it < 2; it++) {
        const int i = tid + it * 256;
        const int r = i >> 3;
        const int c = i & 7;
        const uint32_t so = (uint32_t)(r * ASTR + c * 16);
        CP_ASYNC16(base + so,          Kg  + bhoff + (size_t)(k0 + r) * DK + c * 8);
        CP_ASYNC16(base + KVTILE + so, Vtg + bhoff + (size_t)r * SEQ + k0 + c * 8);
    }
}

__global__ __launch_bounds__(256) void attn_hmma(
    const __half* __restrict__ Qg, const __half* __restrict__ Kg,
    const __half* __restrict__ Vtg, __half* __restrict__ Og)
{
    extern __shared__ char sm[];
    const uint32_t smb = smem_u32(sm);
    const int tid = threadIdx.x;
    const int wid = tid >> 5;
    const int lane = tid & 31;
    const int qb = gridDim.x - 1 - blockIdx.x;
    const int bh = blockIdx.y;
    const int q0 = qb * BQ;
    const size_t bhoff = (size_t)bh * SEQ * DK;
    const int lrow = lane & 15;
    const uint32_t lcol = (uint32_t)((lane >> 4) * 16);
    const int g = lane >> 2;
    const int t = lane & 3;
    const int q0w = q0 + wid * 16;
    const uint32_t kvb = smb + QTILE;
    const int nt = qb * 2 + 2;

    #pragma unroll
    for (int it = 0; it < 4; it++) {
        const int i = tid + it * 256;
        const int r = i >> 3;
        const int c = i & 7;
        CP_ASYNC16(smb + (uint32_t)(r * ASTR + c * 16),
                   Qg + bhoff + (size_t)(q0 + r) * DK + c * 8);
    }
    attn_load_kv(kvb, Kg, Vtg, bhoff, 0, tid);
    CP_COMMIT();
    attn_load_kv(kvb + KVBUF, Kg, Vtg, bhoff, BKV, tid);
    CP_COMMIT();

    uint32_t qf[4][4];
    float oacc[8][4];
    #pragma unroll
    for (int f = 0; f < 8; f++)
        #pragma unroll
        for (int r = 0; r < 4; r++) oacc[f][r] = 0.f;
    float m_i[2] = {-1e30f, -1e30f};
    float l_i[2] = {0.f, 0.f};

    int stage = 0;
    for (int kt = 0; kt < nt; kt++) {
        const int k0 = kt * BKV;
        CP_WAIT(1);
        __syncthreads();
        if (kt + 2 < nt) {
            int ns = stage + 2; if (ns >= 3) ns -= 3;
            attn_load_kv(kvb + (uint32_t)(ns * KVBUF), Kg, Vtg, bhoff, k0 + 2 * BKV, tid);
        }
        CP_COMMIT();

        if (kt == 0) {
            #pragma unroll
            for (int kf = 0; kf < 4; kf++) {
                const uint32_t ro = (uint32_t)((wid * 16 + lrow) * ASTR) + (uint32_t)(kf * 32) + lcol;
                LDMX4(qf[kf][0], qf[kf][1], qf[kf][2], qf[kf][3], smb + ro);
            }
        }

        if (q0w + 15 >= k0) {
            const uint32_t kb = kvb + (uint32_t)(stage * KVBUF);
            const uint32_t vb = kb + KVTILE;

            float s[8][4];
            #pragma unroll
            for (int f = 0; f < 8; f++)
                #pragma unroll
                for (int r = 0; r < 4; r++) s[f][r] = 0.f;

            #pragma unroll
            for (int kf = 0; kf < 4; kf++) {
                const uint32_t ko = (uint32_t)(kf * 32) + lcol;
                #pragma unroll
                for (int p = 0; p < 4; p++) {
                    uint32_t b0, b1, b2, b3;
                    LDMX4(b0, b1, b2, b3, kb + (uint32_t)((p * 16 + lrow) * ASTR) + ko);
                    MMA16816(s[2*p],   qf[kf][0], qf[kf][1], qf[kf][2], qf[kf][3], b0, b2);
                    MMA16816(s[2*p+1], qf[kf][0], qf[kf][1], qf[kf][2], qf[kf][3], b1, b3);
                }
            }

            if (k0 + 63 > q0w) {
                const int r0 = q0w + g, r1 = r0 + 8;
                #pragma unroll
                for (int ni = 0; ni < 8; ni++) {
                    const int c0 = k0 + ni * 8 + t * 2;
                    if (c0     > r0) s[ni][0] = -1e30f;
                    if (c0 + 1 > r0) s[ni][1] = -1e30f;
                    if (c0     > r1) s[ni][2] = -1e30f;
                    if (c0 + 1 > r1) s[ni][3] = -1e30f;
                }
            }

            float rmx0 = -1e30f, rmx1 = -1e30f;
            #pragma unroll
            for (int ni = 0; ni < 8; ni++) {
                rmx0 = fmaxf(rmx0, fmaxf(s[ni][0], s[ni][1]));
                rmx1 = fmaxf(rmx1, fmaxf(s[ni][2], s[ni][3]));
            }
            rmx0 = fmaxf(rmx0, __shfl_xor_sync(0xffffffffu, rmx0, 1));
            rmx0 = fmaxf(rmx0, __shfl_xor_sync(0xffffffffu, rmx0, 2));
            rmx1 = fmaxf(rmx1, __shfl_xor_sync(0xffffffffu, rmx1, 1));
            rmx1 = fmaxf(rmx1, __shfl_xor_sync(0xffffffffu, rmx1, 2));
            const float mn0 = fmaxf(m_i[0], rmx0);
            const float mn1 = fmaxf(m_i[1], rmx1);
            const float sc0 = ex2(m_i[0] - mn0);   // base-2 (Q pre-scaled by log2e)
            const float sc1 = ex2(m_i[1] - mn1);
            float rs0 = 0.f, rs1 = 0.f;
            #pragma unroll
            for (int ni = 0; ni < 8; ni++) {
                s[ni][0] = ex2(s[ni][0] - mn0); rs0 += s[ni][0];
                s[ni][1] = ex2(s[ni][1] - mn0); rs0 += s[ni][1];
                s[ni][2] = ex2(s[ni][2] - mn1); rs1 += s[ni][2];
                s[ni][3] = ex2(s[ni][3] - mn1); rs1 += s[ni][3];
            }
            rs0 += __shfl_xor_sync(0xffffffffu, rs0, 1);
            rs0 += __shfl_xor_sync(0xffffffffu, rs0, 2);
            rs1 += __shfl_xor_sync(0xffffffffu, rs1, 1);
            rs1 += __shfl_xor_sync(0xffffffffu, rs1, 2);
            m_i[0] = mn0; m_i[1] = mn1;
            l_i[0] = l_i[0] * sc0 + rs0;
            l_i[1] = l_i[1] * sc1 + rs1;
            #pragma unroll
            for (int f = 0; f < 8; f++) {
                oacc[f][0] *= sc0; oacc[f][1] *= sc0;
                oacc[f][2] *= sc1; oacc[f][3] *= sc1;
            }

            #pragma unroll
            for (int kf = 0; kf < 4; kf++) {
                const uint32_t pa0 = packh2(s[2*kf][0],   s[2*kf][1]);
                const uint32_t pa1 = packh2(s[2*kf][2],   s[2*kf][3]);
                const uint32_t pa2 = packh2(s[2*kf+1][0], s[2*kf+1][1]);
                const uint32_t pa3 = packh2(s[2*kf+1][2], s[2*kf+1][3]);
                const uint32_t ko = (uint32_t)(kf * 32) + lcol;
                #pragma unroll
                for (int p = 0; p < 4; p++) {
                    uint32_t b0, b1, b2, b3;
                    LDMX4(b0, b1, b2, b3, vb + (uint32_t)((p * 16 + lrow) * ASTR) + ko);
                    MMA16816(oacc[2*p],   pa0, pa1, pa2, pa3, b0, b2);
                    MMA16816(oacc[2*p+1], pa0, pa1, pa2, pa3, b1, b3);
                }
            }
        }
        if (++stage >= 3) stage = 0;
    }

    const float inv0 = 1.0f / l_i[0];
    const float inv1 = 1.0f / l_i[1];
    const int b = bh >> 4, h = bh & 15;
    const int r0 = q0w + g, r1 = r0 + 8;
    #pragma unroll
    for (int ni = 0; ni < 8; ni++) {
        const int col = h * 64 + ni * 8 + t * 2;
        *(__half2*)(Og + (size_t)(b * SEQ + r0) * D_MODEL + col)
            = __floats2half2_rn(oacc[ni][0] * inv0, oacc[ni][1] * inv0);
        *(__half2*)(Og + (size_t)(b * SEQ + r1) * D_MODEL + col)
            = __floats2half2_rn(oacc[ni][2] * inv1, oacc[ni][3] * inv1);
    }
}

// ---------------------------------------------------------------------------
extern "C" void kernel_launch(void* const* d_in, const int* in_sizes, int n_in,
                              void* d_out, int out_size)
{
    const float* x   = (const float*)d_in[0];
    const float* w_q = (const float*)d_in[2];
    const float* b_q = (const float*)d_in[3];
    const float* w_k = (const float*)d_in[4];
    const float* b_k = (const float*)d_in[5];
    const float* w_v = (const float*)d_in[6];
    const float* b_v = (const float*)d_in[7];
    const float* w_o = (const float*)d_in[8];
    const float* b_o = (const float*)d_in[9];
    float* out = (float*)d_out;

    __half *x16, *w4, *qq, *kk, *vt, *oo;
    cudaGetSymbolAddress((void**)&x16, g_x16);
    cudaGetSymbolAddress((void**)&w4, g_w4);
    cudaGetSymbolAddress((void**)&qq, g_q);
    cudaGetSymbolAddress((void**)&kk, g_k);
    cudaGetSymbolAddress((void**)&vt, g_vt);
    cudaGetSymbolAddress((void**)&oo, g_o);

    const size_t WSZ = (size_t)D_MODEL * D_MODEL;
    __half *wo = w4 + 3 * WSZ;

    cudaFuncSetAttribute(gemm_qkv,   cudaFuncAttributeMaxDynamicSharedMemorySize, GEMM_SMEM);
    cudaFuncSetAttribute(gemm_oproj, cudaFuncAttributeMaxDynamicSharedMemorySize, GEMM_SMEM);
    cudaFuncSetAttribute(attn_hmma,  cudaFuncAttributeMaxDynamicSharedMemorySize, ATTN_SMEM);

    prep<<<8192 + 4096, 256>>>(x, w_q, w_k, w_v, w_o, x16, w4);

    gemm_qkv<<<dim3(D_MODEL / 128, M_ROWS / 128, 3), 256, GEMM_SMEM>>>(
        x16, w4, b_q, b_k, b_v, qq, kk, vt);

    attn_hmma<<<dim3(SEQ / BQ, 64), 256, ATTN_SMEM>>>(qq, kk, vt, oo);

    gemm_oproj<<<dim3(D_MODEL / 128, M_ROWS / 128), 256, GEMM_SMEM>>>(oo, wo, b_o, out);
}